// round 1
// baseline (speedup 1.0000x reference)
#include <cuda_runtime.h>
#include <math.h>

#define SQ   2048
#define DIM  1024
#define NH   16
#define HDK  64
#define MLPD 4096

// ---------------- scratch (no allocations allowed) ----------------
__device__ float g_h [SQ * DIM];   // LN output (reused for ln1 and ln2)
__device__ float g_q [SQ * DIM];
__device__ float g_k [SQ * DIM];
__device__ float g_v [SQ * DIM];
__device__ float g_ao[SQ * DIM];   // attention out, [H,S,DK] contiguous
__device__ float g_x1[SQ * DIM];   // x + attn_out @ wo + bo
__device__ float g_f [SQ * MLPD];  // gelu(h2 @ w1 + b1)

// ---------------- layernorm ----------------
__device__ __forceinline__ float block_sum_256(float v, float* sh) {
    int lane = threadIdx.x & 31, w = threadIdx.x >> 5;
    #pragma unroll
    for (int o = 16; o; o >>= 1) v += __shfl_xor_sync(0xffffffffu, v, o);
    __syncthreads();                 // protect sh across repeated calls
    if (lane == 0) sh[w] = v;
    __syncthreads();
    float r = 0.f;
    #pragma unroll
    for (int i = 0; i < 8; i++) r += sh[i];
    return r;
}

__global__ void ln_kernel(const float* __restrict__ x, const float* __restrict__ g,
                          const float* __restrict__ b, float* __restrict__ out) {
    __shared__ float sh[8];
    int row = blockIdx.x;
    const float* xr = x + (size_t)row * DIM;
    int t = threadIdx.x;
    float v0[4];
    float s = 0.f;
    #pragma unroll
    for (int u = 0; u < 4; u++) { v0[u] = xr[t + u * 256]; s += v0[u]; }
    s = block_sum_256(s, sh);
    float mean = s * (1.0f / DIM);
    float vs = 0.f;
    #pragma unroll
    for (int u = 0; u < 4; u++) { float d = v0[u] - mean; vs += d * d; }
    vs = block_sum_256(vs, sh);
    float rstd = rsqrtf(vs * (1.0f / DIM) + 1e-5f);
    #pragma unroll
    for (int u = 0; u < 4; u++) {
        int c = t + u * 256;
        out[(size_t)row * DIM + c] = (v0[u] - mean) * rstd * g[c] + b[c];
    }
}

// ---------------- SGEMM: C = A[MxK] @ B[KxN] + bias (+gelu) (+res) ----------------
// 128x128 block tile, BK=8, 8x8 per thread (quadrant split), 256 threads.
__global__ __launch_bounds__(256)
void sgemm_kernel(const float* __restrict__ A, const float* __restrict__ B,
                  const float* __restrict__ bias, const float* __restrict__ res,
                  float* __restrict__ C, int M, int N, int K, int gelu) {
    __shared__ float As[8][128];
    __shared__ float Bs[8][128];
    const int tid = threadIdx.x;
    const int bm = blockIdx.y * 128;
    const int bn = blockIdx.x * 128;
    const int tr = tid >> 4;          // 0..15
    const int tc = tid & 15;          // 0..15
    const int aRow = tid >> 1;        // 0..127
    const int aCol = (tid & 1) * 4;   // 0 or 4
    const int bRow = tid >> 5;        // 0..7
    const int bCol = (tid & 31) * 4;  // 0..124

    float acc[8][8];
    #pragma unroll
    for (int i = 0; i < 8; i++)
        #pragma unroll
        for (int j = 0; j < 8; j++) acc[i][j] = 0.f;

    for (int k0 = 0; k0 < K; k0 += 8) {
        float4 av = *(const float4*)(A + (size_t)(bm + aRow) * K + k0 + aCol);
        As[aCol + 0][aRow] = av.x; As[aCol + 1][aRow] = av.y;
        As[aCol + 2][aRow] = av.z; As[aCol + 3][aRow] = av.w;
        float4 bv = *(const float4*)(B + (size_t)(k0 + bRow) * N + bn + bCol);
        *(float4*)&Bs[bRow][bCol] = bv;
        __syncthreads();
        #pragma unroll
        for (int k = 0; k < 8; k++) {
            float af[8], bf[8];
            *(float4*)&af[0] = *(const float4*)&As[k][tr * 4];
            *(float4*)&af[4] = *(const float4*)&As[k][64 + tr * 4];
            *(float4*)&bf[0] = *(const float4*)&Bs[k][tc * 4];
            *(float4*)&bf[4] = *(const float4*)&Bs[k][64 + tc * 4];
            #pragma unroll
            for (int i = 0; i < 8; i++)
                #pragma unroll
                for (int j = 0; j < 8; j++)
                    acc[i][j] += af[i] * bf[j];
        }
        __syncthreads();
    }

    #pragma unroll
    for (int i = 0; i < 8; i++) {
        int r = bm + ((i < 4) ? (tr * 4 + i) : (64 + tr * 4 + i - 4));
        #pragma unroll
        for (int j = 0; j < 8; j++) {
            int c = bn + ((j < 4) ? (tc * 4 + j) : (64 + tc * 4 + j - 4));
            float v = acc[i][j] + bias[c];
            if (gelu) v = 0.5f * v * (1.0f + erff(v * 0.70710678118654752f));
            if (res)  v += res[(size_t)r * N + c];
            C[(size_t)r * N + c] = v;
        }
    }
}

// ---------------- flash attention (fp32, 64x64 tiles, online softmax) ----------------
// Q,K,V: [S, D] row-major; head h = cols [h*64, h*64+64)
// O: [H, S, DK] contiguous (= reference's reshape(S, D) without transpose-back)
__global__ __launch_bounds__(256)
void attn_kernel(const float* __restrict__ Qg, const float* __restrict__ Kg,
                 const float* __restrict__ Vg, float* __restrict__ O) {
    __shared__ float Qs[64][64];
    __shared__ float KP[64][64];   // K transposed [d][key], later reused as P [q][key]
    __shared__ float Vs[64][64];

    const int h  = blockIdx.y;
    const int q0 = blockIdx.x * 64;
    const int tid = threadIdx.x;
    const int r0 = (tid >> 4) * 4;   // query-row group (4 rows)
    const int c0 = (tid & 15) * 4;   // col group (4 cols)
    const int lr = tid >> 2;         // load row 0..63
    const int lc = (tid & 3) * 16;   // load col base

    // load Q tile, pre-scaled by 1/sqrt(DK)
    #pragma unroll
    for (int u = 0; u < 4; u++) {
        float4 qv = *(const float4*)(Qg + (size_t)(q0 + lr) * DIM + h * HDK + lc + u * 4);
        qv.x *= 0.125f; qv.y *= 0.125f; qv.z *= 0.125f; qv.w *= 0.125f;
        *(float4*)&Qs[lr][lc + u * 4] = qv;
    }

    float m[4], l[4], acc[4][4];
    #pragma unroll
    for (int i = 0; i < 4; i++) {
        m[i] = -1e30f; l[i] = 0.f;
        #pragma unroll
        for (int j = 0; j < 4; j++) acc[i][j] = 0.f;
    }

    for (int kt = 0; kt < SQ; kt += 64) {
        __syncthreads();  // prev P@V done (and Qs visible on first iter)
        // load K (transposed into KP) and V
        #pragma unroll
        for (int u = 0; u < 4; u++) {
            float4 kv = *(const float4*)(Kg + (size_t)(kt + lr) * DIM + h * HDK + lc + u * 4);
            KP[lc + u * 4 + 0][lr] = kv.x; KP[lc + u * 4 + 1][lr] = kv.y;
            KP[lc + u * 4 + 2][lr] = kv.z; KP[lc + u * 4 + 3][lr] = kv.w;
            float4 vv = *(const float4*)(Vg + (size_t)(kt + lr) * DIM + h * HDK + lc + u * 4);
            *(float4*)&Vs[lr][lc + u * 4] = vv;
        }
        __syncthreads();

        // s = (Q/8) @ K^T
        float sv[4][4];
        #pragma unroll
        for (int i = 0; i < 4; i++)
            #pragma unroll
            for (int j = 0; j < 4; j++) sv[i][j] = 0.f;
        #pragma unroll 8
        for (int d = 0; d < 64; d++) {
            float a[4], bb[4];
            #pragma unroll
            for (int i = 0; i < 4; i++) a[i] = Qs[r0 + i][d];
            #pragma unroll
            for (int j = 0; j < 4; j++) bb[j] = KP[d][c0 + j];
            #pragma unroll
            for (int i = 0; i < 4; i++)
                #pragma unroll
                for (int j = 0; j < 4; j++)
                    sv[i][j] += a[i] * bb[j];
        }

        // online softmax (row reductions across the 16-thread row group)
        float p[4][4];
        #pragma unroll
        for (int i = 0; i < 4; i++) {
            float mx = sv[i][0];
            mx = fmaxf(mx, sv[i][1]); mx = fmaxf(mx, sv[i][2]); mx = fmaxf(mx, sv[i][3]);
            #pragma unroll
            for (int o = 1; o < 16; o <<= 1)
                mx = fmaxf(mx, __shfl_xor_sync(0xffffffffu, mx, o));
            float mn = fmaxf(m[i], mx);
            float sc = expf(m[i] - mn);
            float rs = 0.f;
            #pragma unroll
            for (int j = 0; j < 4; j++) { p[i][j] = expf(sv[i][j] - mn); rs += p[i][j]; }
            #pragma unroll
            for (int o = 1; o < 16; o <<= 1)
                rs += __shfl_xor_sync(0xffffffffu, rs, o);
            l[i] = l[i] * sc + rs;
            m[i] = mn;
            #pragma unroll
            for (int j = 0; j < 4; j++) acc[i][j] *= sc;
        }

        __syncthreads();  // everyone done reading KP as K
        #pragma unroll
        for (int i = 0; i < 4; i++)
            *(float4*)&KP[r0 + i][c0] = make_float4(p[i][0], p[i][1], p[i][2], p[i][3]);
        __syncthreads();

        // acc += P @ V
        #pragma unroll 8
        for (int kk = 0; kk < 64; kk++) {
            float a[4], bb[4];
            #pragma unroll
            for (int i = 0; i < 4; i++) a[i] = KP[r0 + i][kk];
            #pragma unroll
            for (int j = 0; j < 4; j++) bb[j] = Vs[kk][c0 + j];
            #pragma unroll
            for (int i = 0; i < 4; i++)
                #pragma unroll
                for (int j = 0; j < 4; j++)
                    acc[i][j] += a[i] * bb[j];
        }
    }

    // O[h][q][dk] = acc / l
    #pragma unroll
    for (int i = 0; i < 4; i++) {
        float inv = 1.0f / l[i];
        #pragma unroll
        for (int j = 0; j < 4; j++)
            O[(size_t)h * SQ * HDK + (size_t)(q0 + r0 + i) * HDK + c0 + j] = acc[i][j] * inv;
    }
}

// ---------------- launch ----------------
extern "C" void kernel_launch(void* const* d_in, const int* in_sizes, int n_in,
                              void* d_out, int out_size) {
    const float* x     = (const float*)d_in[0];
    const float* wq    = (const float*)d_in[1];
    const float* bq    = (const float*)d_in[2];
    const float* wk    = (const float*)d_in[3];
    const float* bk    = (const float*)d_in[4];
    const float* wv    = (const float*)d_in[5];
    const float* bv    = (const float*)d_in[6];
    const float* wo    = (const float*)d_in[7];
    const float* bo    = (const float*)d_in[8];
    const float* w1    = (const float*)d_in[9];
    const float* b1    = (const float*)d_in[10];
    const float* w2    = (const float*)d_in[11];
    const float* b2    = (const float*)d_in[12];
    const float* ln1_g = (const float*)d_in[13];
    const float* ln1_b = (const float*)d_in[14];
    const float* ln2_g = (const float*)d_in[15];
    const float* ln2_b = (const float*)d_in[16];
    float* out = (float*)d_out;

    float *h, *q, *k, *v, *ao, *x1, *f;
    cudaGetSymbolAddress((void**)&h,  g_h);
    cudaGetSymbolAddress((void**)&q,  g_q);
    cudaGetSymbolAddress((void**)&k,  g_k);
    cudaGetSymbolAddress((void**)&v,  g_v);
    cudaGetSymbolAddress((void**)&ao, g_ao);
    cudaGetSymbolAddress((void**)&x1, g_x1);
    cudaGetSymbolAddress((void**)&f,  g_f);

    dim3 gD(DIM / 128, SQ / 128);    // N=1024 GEMMs
    dim3 gM(MLPD / 128, SQ / 128);   // N=4096 GEMM

    // LN1
    ln_kernel<<<SQ, 256>>>(x, ln1_g, ln1_b, h);
    // QKV projections
    sgemm_kernel<<<gD, 256>>>(h, wq, bq, nullptr, q, SQ, DIM, DIM, 0);
    sgemm_kernel<<<gD, 256>>>(h, wk, bk, nullptr, k, SQ, DIM, DIM, 0);
    sgemm_kernel<<<gD, 256>>>(h, wv, bv, nullptr, v, SQ, DIM, DIM, 0);
    // attention
    attn_kernel<<<dim3(SQ / 64, NH), 256>>>(q, k, v, ao);
    // O projection + residual(x)
    sgemm_kernel<<<gD, 256>>>(ao, wo, bo, x, x1, SQ, DIM, DIM, 0);
    // LN2
    ln_kernel<<<SQ, 256>>>(x1, ln2_g, ln2_b, h);
    // FFN1 + exact GELU
    sgemm_kernel<<<gM, 256>>>(h, w1, b1, nullptr, f, SQ, MLPD, DIM, 1);
    // FFN2 + residual(x1) -> out
    sgemm_kernel<<<gD, 256>>>(f, w2, b2, x1, out, SQ, DIM, MLPD, 0);
}

// round 3
// speedup vs baseline: 1.9754x; 1.9754x over previous
#include <cuda_runtime.h>
#include <cuda_bf16.h>
#include <math.h>
#include <stdint.h>

#define SQ   2048
#define DIM  1024
#define NH   16
#define HDK  64
#define MLPD 4096
#define QKVN 3072

// ---------------- scratch (no allocations allowed) ----------------
__device__ unsigned short g_h_hi [SQ*DIM],  g_h_lo [SQ*DIM];
__device__ float          g_qkv  [SQ*QKVN];
__device__ unsigned short g_ao_hi[SQ*DIM],  g_ao_lo[SQ*DIM];
__device__ float          g_x1   [SQ*DIM];
__device__ unsigned short g_f_hi [SQ*MLPD], g_f_lo [SQ*MLPD];
__device__ unsigned short g_wqkv_hi[QKVN*DIM], g_wqkv_lo[QKVN*DIM];
__device__ unsigned short g_wo_hi [DIM*DIM],   g_wo_lo [DIM*DIM];
__device__ unsigned short g_w1_hi [MLPD*DIM],  g_w1_lo [MLPD*DIM];
__device__ unsigned short g_w2_hi [DIM*MLPD],  g_w2_lo [DIM*MLPD];
__device__ float          g_bqkv[QKVN];

// ---------------- helpers ----------------
__device__ __forceinline__ uint32_t smem_u32(const void* p) {
    uint32_t a;
    asm("{ .reg .u64 t; cvta.to.shared.u64 t, %1; cvt.u32.u64 %0, t; }" : "=r"(a) : "l"(p));
    return a;
}

__device__ __forceinline__ void cp_async16(uint32_t sdst, const void* gsrc) {
    asm volatile("cp.async.cg.shared.global [%0], [%1], 16;" :: "r"(sdst), "l"(gsrc) : "memory");
}
#define CP_COMMIT() asm volatile("cp.async.commit_group;" ::: "memory")
#define CP_WAIT(n)  asm volatile("cp.async.wait_group %0;" :: "n"(n) : "memory")

#define LDSM4(r, addr) \
    asm volatile("ldmatrix.sync.aligned.m8n8.x4.shared.b16 {%0,%1,%2,%3}, [%4];" \
        : "=r"((r)[0]), "=r"((r)[1]), "=r"((r)[2]), "=r"((r)[3]) : "r"(addr))

#define MMA_BF16(c, a, b0, b1) \
    asm volatile("mma.sync.aligned.m16n8k16.row.col.f32.bf16.bf16.f32 " \
        "{%0,%1,%2,%3}, {%4,%5,%6,%7}, {%8,%9}, {%0,%1,%2,%3};" \
        : "+f"((c)[0]), "+f"((c)[1]), "+f"((c)[2]), "+f"((c)[3]) \
        : "r"((a)[0]), "r"((a)[1]), "r"((a)[2]), "r"((a)[3]), "r"(b0), "r"(b1))

__device__ __forceinline__ void split_bf16(float v, unsigned short& hi, unsigned short& lo) {
    __nv_bfloat16 h = __float2bfloat16(v);
    float r = v - __bfloat162float(h);
    hi = __bfloat16_as_ushort(h);
    lo = __bfloat16_as_ushort(__float2bfloat16(r));
}

// ---------------- layernorm -> bf16 hi/lo ----------------
__device__ __forceinline__ float block_sum_256(float v, float* sh) {
    int lane = threadIdx.x & 31, w = threadIdx.x >> 5;
    #pragma unroll
    for (int o = 16; o; o >>= 1) v += __shfl_xor_sync(0xffffffffu, v, o);
    __syncthreads();
    if (lane == 0) sh[w] = v;
    __syncthreads();
    float r = 0.f;
    #pragma unroll
    for (int i = 0; i < 8; i++) r += sh[i];
    return r;
}

__global__ void ln_split_kernel(const float* __restrict__ x, const float* __restrict__ g,
                                const float* __restrict__ b,
                                unsigned short* __restrict__ ohi, unsigned short* __restrict__ olo) {
    __shared__ float sh[8];
    int row = blockIdx.x;
    const float* xr = x + (size_t)row * DIM;
    int t = threadIdx.x;
    float v0[4];
    float s = 0.f;
    #pragma unroll
    for (int u = 0; u < 4; u++) { v0[u] = xr[t + u * 256]; s += v0[u]; }
    s = block_sum_256(s, sh);
    float mean = s * (1.0f / DIM);
    float vs = 0.f;
    #pragma unroll
    for (int u = 0; u < 4; u++) { float d = v0[u] - mean; vs += d * d; }
    vs = block_sum_256(vs, sh);
    float rstd = rsqrtf(vs * (1.0f / DIM) + 1e-5f);
    #pragma unroll
    for (int u = 0; u < 4; u++) {
        int c = t + u * 256;
        float v = (v0[u] - mean) * rstd * g[c] + b[c];
        unsigned short h, l;
        split_bf16(v, h, l);
        ohi[(size_t)row * DIM + c] = h;
        olo[(size_t)row * DIM + c] = l;
    }
}

// ---------------- weight transpose + split: in[R,C] fp32 -> out[C,R] bf16 hi/lo ----------------
__global__ void transpose_split_kernel(const float* __restrict__ in, int R, int C,
                                       unsigned short* __restrict__ hi, unsigned short* __restrict__ lo) {
    __shared__ float t[32][33];
    int c0 = blockIdx.x * 32, r0 = blockIdx.y * 32;
    #pragma unroll
    for (int u = 0; u < 4; u++) {
        int r = r0 + threadIdx.y + u * 8;
        t[threadIdx.y + u * 8][threadIdx.x] = in[(size_t)r * C + c0 + threadIdx.x];
    }
    __syncthreads();
    #pragma unroll
    for (int u = 0; u < 4; u++) {
        int c = c0 + threadIdx.y + u * 8;
        float v = t[threadIdx.x][threadIdx.y + u * 8];
        unsigned short h, l;
        split_bf16(v, h, l);
        hi[(size_t)c * R + r0 + threadIdx.x] = h;
        lo[(size_t)c * R + r0 + threadIdx.x] = l;
    }
}

__global__ void concat_bias_kernel(const float* __restrict__ bq, const float* __restrict__ bk,
                                   const float* __restrict__ bv, float* __restrict__ out) {
    int i = blockIdx.x * 256 + threadIdx.x;
    if (i < DIM) out[i] = bq[i];
    else if (i < 2 * DIM) out[i] = bk[i - DIM];
    else if (i < 3 * DIM) out[i] = bv[i - 2 * DIM];
}

// ---------------- mma.sync bf16x3 GEMM ----------------
// C[M,N] = A[M,K] @ B^T (B stored [N,K]), A/B as bf16 hi/lo pairs, fp32 accum.
// 128x128 CTA tile, BK=32, double buffered cp.async, 8 warps of 64x32.
// smem tile: 128 rows x 40 halves (32 data + 8 pad) = 10240 B.
#define TILEB 10240u
#define GEMM_SMEM (8 * 10240)

__global__ __launch_bounds__(256)
void gemm_mma_kernel(const unsigned short* __restrict__ Ahi, const unsigned short* __restrict__ Alo,
                     const unsigned short* __restrict__ Bhi, const unsigned short* __restrict__ Blo,
                     const float* __restrict__ bias, const float* __restrict__ res,
                     float* __restrict__ outF,
                     unsigned short* __restrict__ outHi, unsigned short* __restrict__ outLo,
                     int N, int K, int gelu) {
    extern __shared__ char smem[];
    const uint32_t sb = smem_u32(smem);
    const int tid  = threadIdx.x;
    const int wid  = tid >> 5;
    const int lane = tid & 31;
    const int wm = wid >> 2;          // 0..1
    const int wn = wid & 3;           // 0..3
    const int bm = blockIdx.y * 128;
    const int bn = blockIdx.x * 128;
    const int g  = lane >> 2;
    const int t4 = lane & 3;

    // ldmatrix lane-relative byte offsets (row stride 80B)
    const uint32_t aOff = (uint32_t)((((lane >> 3) & 1) * 8 + (lane & 7)) * 80 + (lane >> 4) * 16);
    const uint32_t bOff = (uint32_t)(((lane >> 4) * 8 + (lane & 7)) * 80 + ((lane >> 3) & 1) * 16);

    float acc[4][4][4];
    #pragma unroll
    for (int i = 0; i < 4; i++)
        #pragma unroll
        for (int j = 0; j < 4; j++)
            #pragma unroll
            for (int q = 0; q < 4; q++) acc[i][j][q] = 0.f;

    const int NCH = K >> 5;
    const unsigned short* gsrc[4] = {Ahi, Alo, Bhi, Blo};
    const int rbase[4] = {bm, bm, bn, bn};

    // --- load chunk into stage ---
    auto load_chunk = [&](int stage, int k0) {
        #pragma unroll
        for (int t = 0; t < 4; t++) {
            uint32_t dst = sb + (uint32_t)(stage * 4 + t) * TILEB;
            const unsigned short* gp = gsrc[t];
            #pragma unroll
            for (int u = 0; u < 2; u++) {
                int idx = tid + 256 * u;         // 0..511
                int r = idx >> 2;
                int cc = idx & 3;                // 16B chunk in row
                cp_async16(dst + (uint32_t)(r * 80 + cc * 16),
                           gp + (size_t)(rbase[t] + r) * K + k0 + cc * 8);
            }
        }
        CP_COMMIT();
    };

    load_chunk(0, 0);

    for (int i = 0; i < NCH; i++) {
        if (i + 1 < NCH) { load_chunk((i + 1) & 1, (i + 1) * 32); CP_WAIT(1); }
        else             { CP_WAIT(0); }
        __syncthreads();

        const uint32_t base = sb + (uint32_t)((i & 1) * 4) * TILEB;
        const uint32_t aHiB = base,            aLoB = base + TILEB;
        const uint32_t bHiB = base + 2*TILEB,  bLoB = base + 3*TILEB;

        #pragma unroll
        for (int ks = 0; ks < 2; ks++) {
            uint32_t bh[2][4], bl[2][4];
            #pragma unroll
            for (int np = 0; np < 2; np++) {
                uint32_t o = (uint32_t)((wn * 32 + np * 16) * 80 + ks * 32) + bOff;
                LDSM4(bh[np], bHiB + o);
                LDSM4(bl[np], bLoB + o);
            }
            #pragma unroll
            for (int mt = 0; mt < 4; mt++) {
                uint32_t ah[4], al[4];
                uint32_t o = (uint32_t)((wm * 64 + mt * 16) * 80 + ks * 32) + aOff;
                LDSM4(ah, aHiB + o);
                LDSM4(al, aLoB + o);
                #pragma unroll
                for (int nt = 0; nt < 4; nt++) {
                    int np = nt >> 1, sub = (nt & 1) * 2;
                    uint32_t b0h = bh[np][sub], b1h = bh[np][sub + 1];
                    uint32_t b0l = bl[np][sub], b1l = bl[np][sub + 1];
                    MMA_BF16(acc[mt][nt], ah, b0h, b1h);
                    MMA_BF16(acc[mt][nt], ah, b0l, b1l);
                    MMA_BF16(acc[mt][nt], al, b0h, b1h);
                }
            }
        }
        __syncthreads();
    }

    // --- epilogue ---
    #pragma unroll
    for (int mt = 0; mt < 4; mt++) {
        int r0 = bm + wm * 64 + mt * 16 + g;
        #pragma unroll
        for (int nt = 0; nt < 4; nt++) {
            int c = bn + wn * 32 + nt * 8 + t4 * 2;
            float v[4];
            v[0] = acc[mt][nt][0] + bias[c];
            v[1] = acc[mt][nt][1] + bias[c + 1];
            v[2] = acc[mt][nt][2] + bias[c];
            v[3] = acc[mt][nt][3] + bias[c + 1];
            if (gelu) {
                #pragma unroll
                for (int q = 0; q < 4; q++)
                    v[q] = 0.5f * v[q] * (1.0f + erff(v[q] * 0.70710678118654752f));
            }
            if (res) {
                v[0] += res[(size_t)r0 * N + c];
                v[1] += res[(size_t)r0 * N + c + 1];
                v[2] += res[(size_t)(r0 + 8) * N + c];
                v[3] += res[(size_t)(r0 + 8) * N + c + 1];
            }
            if (outF) {
                *(float2*)(outF + (size_t)r0 * N + c)       = make_float2(v[0], v[1]);
                *(float2*)(outF + (size_t)(r0 + 8) * N + c) = make_float2(v[2], v[3]);
            } else {
                unsigned short h0, l0, h1, l1;
                split_bf16(v[0], h0, l0); split_bf16(v[1], h1, l1);
                *(uint32_t*)(outHi + (size_t)r0 * N + c) = (uint32_t)h0 | ((uint32_t)h1 << 16);
                *(uint32_t*)(outLo + (size_t)r0 * N + c) = (uint32_t)l0 | ((uint32_t)l1 << 16);
                split_bf16(v[2], h0, l0); split_bf16(v[3], h1, l1);
                *(uint32_t*)(outHi + (size_t)(r0 + 8) * N + c) = (uint32_t)h0 | ((uint32_t)h1 << 16);
                *(uint32_t*)(outLo + (size_t)(r0 + 8) * N + c) = (uint32_t)l0 | ((uint32_t)l1 << 16);
            }
        }
    }
}

// ---------------- flash attention (fp32) -> bf16 hi/lo output ----------------
__global__ __launch_bounds__(256)
void attn_kernel(const float* __restrict__ Qg, const float* __restrict__ Kg,
                 const float* __restrict__ Vg, int ldq,
                 unsigned short* __restrict__ Ohi, unsigned short* __restrict__ Olo) {
    __shared__ float Qs[64][64];
    __shared__ float KP[64][64];
    __shared__ float Vs[64][64];

    const int h  = blockIdx.y;
    const int q0 = blockIdx.x * 64;
    const int tid = threadIdx.x;
    const int r0 = (tid >> 4) * 4;
    const int c0 = (tid & 15) * 4;
    const int lr = tid >> 2;
    const int lc = (tid & 3) * 16;

    #pragma unroll
    for (int u = 0; u < 4; u++) {
        float4 qv = *(const float4*)(Qg + (size_t)(q0 + lr) * ldq + h * HDK + lc + u * 4);
        qv.x *= 0.125f; qv.y *= 0.125f; qv.z *= 0.125f; qv.w *= 0.125f;
        *(float4*)&Qs[lr][lc + u * 4] = qv;
    }

    float m[4], l[4], acc[4][4];
    #pragma unroll
    for (int i = 0; i < 4; i++) {
        m[i] = -1e30f; l[i] = 0.f;
        #pragma unroll
        for (int j = 0; j < 4; j++) acc[i][j] = 0.f;
    }

    for (int kt = 0; kt < SQ; kt += 64) {
        __syncthreads();
        #pragma unroll
        for (int u = 0; u < 4; u++) {
            float4 kv = *(const float4*)(Kg + (size_t)(kt + lr) * ldq + h * HDK + lc + u * 4);
            KP[lc + u * 4 + 0][lr] = kv.x; KP[lc + u * 4 + 1][lr] = kv.y;
            KP[lc + u * 4 + 2][lr] = kv.z; KP[lc + u * 4 + 3][lr] = kv.w;
            float4 vv = *(const float4*)(Vg + (size_t)(kt + lr) * ldq + h * HDK + lc + u * 4);
            *(float4*)&Vs[lr][lc + u * 4] = vv;
        }
        __syncthreads();

        float sv[4][4];
        #pragma unroll
        for (int i = 0; i < 4; i++)
            #pragma unroll
            for (int j = 0; j < 4; j++) sv[i][j] = 0.f;
        #pragma unroll 8
        for (int d = 0; d < 64; d++) {
            float a[4], bb[4];
            #pragma unroll
            for (int i = 0; i < 4; i++) a[i] = Qs[r0 + i][d];
            #pragma unroll
            for (int j = 0; j < 4; j++) bb[j] = KP[d][c0 + j];
            #pragma unroll
            for (int i = 0; i < 4; i++)
                #pragma unroll
                for (int j = 0; j < 4; j++)
                    sv[i][j] += a[i] * bb[j];
        }

        float p[4][4];
        #pragma unroll
        for (int i = 0; i < 4; i++) {
            float mx = sv[i][0];
            mx = fmaxf(mx, sv[i][1]); mx = fmaxf(mx, sv[i][2]); mx = fmaxf(mx, sv[i][3]);
            #pragma unroll
            for (int o = 1; o < 16; o <<= 1)
                mx = fmaxf(mx, __shfl_xor_sync(0xffffffffu, mx, o));
            float mn = fmaxf(m[i], mx);
            float sc = expf(m[i] - mn);
            float rs = 0.f;
            #pragma unroll
            for (int j = 0; j < 4; j++) { p[i][j] = expf(sv[i][j] - mn); rs += p[i][j]; }
            #pragma unroll
            for (int o = 1; o < 16; o <<= 1)
                rs += __shfl_xor_sync(0xffffffffu, rs, o);
            l[i] = l[i] * sc + rs;
            m[i] = mn;
            #pragma unroll
            for (int j = 0; j < 4; j++) acc[i][j] *= sc;
        }

        __syncthreads();
        #pragma unroll
        for (int i = 0; i < 4; i++)
            *(float4*)&KP[r0 + i][c0] = make_float4(p[i][0], p[i][1], p[i][2], p[i][3]);
        __syncthreads();

        #pragma unroll 8
        for (int kk = 0; kk < 64; kk++) {
            float a[4], bb[4];
            #pragma unroll
            for (int i = 0; i < 4; i++) a[i] = KP[r0 + i][kk];
            #pragma unroll
            for (int j = 0; j < 4; j++) bb[j] = Vs[kk][c0 + j];
            #pragma unroll
            for (int i = 0; i < 4; i++)
                #pragma unroll
                for (int j = 0; j < 4; j++)
                    acc[i][j] += a[i] * bb[j];
        }
    }

    #pragma unroll
    for (int i = 0; i < 4; i++) {
        float inv = 1.0f / l[i];
        size_t base = (size_t)h * SQ * HDK + (size_t)(q0 + r0 + i) * HDK + c0;
        #pragma unroll
        for (int j = 0; j < 4; j++) {
            unsigned short hh, ll;
            split_bf16(acc[i][j] * inv, hh, ll);
            Ohi[base + j] = hh;
            Olo[base + j] = ll;
        }
    }
}

// ---------------- launch ----------------
extern "C" void kernel_launch(void* const* d_in, const int* in_sizes, int n_in,
                              void* d_out, int out_size) {
    const float* x     = (const float*)d_in[0];
    const float* wq    = (const float*)d_in[1];
    const float* bq    = (const float*)d_in[2];
    const float* wk    = (const float*)d_in[3];
    const float* bk    = (const float*)d_in[4];
    const float* wv    = (const float*)d_in[5];
    const float* bv    = (const float*)d_in[6];
    const float* wo    = (const float*)d_in[7];
    const float* bo    = (const float*)d_in[8];
    const float* w1    = (const float*)d_in[9];
    const float* b1    = (const float*)d_in[10];
    const float* w2    = (const float*)d_in[11];
    const float* b2    = (const float*)d_in[12];
    const float* ln1_g = (const float*)d_in[13];
    const float* ln1_b = (const float*)d_in[14];
    const float* ln2_g = (const float*)d_in[15];
    const float* ln2_b = (const float*)d_in[16];
    float* out = (float*)d_out;

    unsigned short *hhi, *hlo, *aohi, *aolo, *fhi, *flo;
    unsigned short *wqkvh, *wqkvl, *woh, *wol, *w1h, *w1l, *w2h, *w2l;
    float *qkv, *x1, *bqkv;
    cudaGetSymbolAddress((void**)&hhi,  g_h_hi);  cudaGetSymbolAddress((void**)&hlo,  g_h_lo);
    cudaGetSymbolAddress((void**)&qkv,  g_qkv);
    cudaGetSymbolAddress((void**)&aohi, g_ao_hi); cudaGetSymbolAddress((void**)&aolo, g_ao_lo);
    cudaGetSymbolAddress((void**)&x1,   g_x1);
    cudaGetSymbolAddress((void**)&fhi,  g_f_hi);  cudaGetSymbolAddress((void**)&flo,  g_f_lo);
    cudaGetSymbolAddress((void**)&wqkvh, g_wqkv_hi); cudaGetSymbolAddress((void**)&wqkvl, g_wqkv_lo);
    cudaGetSymbolAddress((void**)&woh,  g_wo_hi); cudaGetSymbolAddress((void**)&wol,  g_wo_lo);
    cudaGetSymbolAddress((void**)&w1h,  g_w1_hi); cudaGetSymbolAddress((void**)&w1l,  g_w1_lo);
    cudaGetSymbolAddress((void**)&w2h,  g_w2_hi); cudaGetSymbolAddress((void**)&w2l,  g_w2_lo);
    cudaGetSymbolAddress((void**)&bqkv, g_bqkv);

    cudaFuncSetAttribute(gemm_mma_kernel,
                         cudaFuncAttributeMaxDynamicSharedMemorySize, GEMM_SMEM);

    dim3 tb(32, 8);

    // weight prep (transpose + bf16 split)
    transpose_split_kernel<<<dim3(DIM/32,  DIM/32),  tb>>>(wq, DIM,  DIM,  wqkvh,             wqkvl);
    transpose_split_kernel<<<dim3(DIM/32,  DIM/32),  tb>>>(wk, DIM,  DIM,  wqkvh + DIM*DIM,   wqkvl + DIM*DIM);
    transpose_split_kernel<<<dim3(DIM/32,  DIM/32),  tb>>>(wv, DIM,  DIM,  wqkvh + 2*DIM*DIM, wqkvl + 2*DIM*DIM);
    transpose_split_kernel<<<dim3(DIM/32,  DIM/32),  tb>>>(wo, DIM,  DIM,  woh, wol);
    transpose_split_kernel<<<dim3(MLPD/32, DIM/32),  tb>>>(w1, DIM,  MLPD, w1h, w1l);
    transpose_split_kernel<<<dim3(DIM/32,  MLPD/32), tb>>>(w2, MLPD, DIM,  w2h, w2l);
    concat_bias_kernel<<<QKVN/256, 256>>>(bq, bk, bv, bqkv);

    // LN1 -> split
    ln_split_kernel<<<SQ, 256>>>(x, ln1_g, ln1_b, hhi, hlo);

    // QKV fused GEMM: [2048,1024] @ [1024,3072] -> fp32 qkv
    gemm_mma_kernel<<<dim3(QKVN/128, SQ/128), 256, GEMM_SMEM>>>(
        hhi, hlo, wqkvh, wqkvl, bqkv, nullptr, qkv, nullptr, nullptr, QKVN, DIM, 0);

    // attention -> ao split ([H,S,DK] layout)
    attn_kernel<<<dim3(SQ/64, NH), 256>>>(qkv, qkv + DIM, qkv + 2*DIM, QKVN, aohi, aolo);

    // O-proj + residual(x) -> x1 fp32
    gemm_mma_kernel<<<dim3(DIM/128, SQ/128), 256, GEMM_SMEM>>>(
        aohi, aolo, woh, wol, bo, x, x1, nullptr, nullptr, DIM, DIM, 0);

    // LN2 -> split
    ln_split_kernel<<<SQ, 256>>>(x1, ln2_g, ln2_b, hhi, hlo);

    // FFN1 + GELU -> f split
    gemm_mma_kernel<<<dim3(MLPD/128, SQ/128), 256, GEMM_SMEM>>>(
        hhi, hlo, w1h, w1l, b1, nullptr, nullptr, fhi, flo, MLPD, DIM, 1);

    // FFN2 + residual(x1) -> out fp32
    gemm_mma_kernel<<<dim3(DIM/128, SQ/128), 256, GEMM_SMEM>>>(
        fhi, flo, w2h, w2l, b2, x1, out, nullptr, nullptr, DIM, MLPD, 0);
}

// round 4
// speedup vs baseline: 3.0294x; 1.5336x over previous
#include <cuda_runtime.h>
#include <cuda_bf16.h>
#include <math.h>
#include <stdint.h>

#define SQ   2048
#define DIM  1024
#define NH   16
#define HDK  64
#define MLPD 4096
#define QKVN 3072

// ---------------- scratch (no allocations allowed) ----------------
__device__ unsigned short g_h_hi [SQ*DIM],  g_h_lo [SQ*DIM];
__device__ unsigned short g_qkv_hi[SQ*QKVN], g_qkv_lo[SQ*QKVN];
__device__ unsigned short g_ao_hi[SQ*DIM],  g_ao_lo[SQ*DIM];
__device__ float          g_x1   [SQ*DIM];
__device__ unsigned short g_f_hi [SQ*MLPD], g_f_lo [SQ*MLPD];
__device__ unsigned short g_wqkv_hi[QKVN*DIM], g_wqkv_lo[QKVN*DIM];
__device__ unsigned short g_wo_hi [DIM*DIM],   g_wo_lo [DIM*DIM];
__device__ unsigned short g_w1_hi [MLPD*DIM],  g_w1_lo [MLPD*DIM];
__device__ unsigned short g_w2_hi [DIM*MLPD],  g_w2_lo [DIM*MLPD];
__device__ float          g_bqkv[QKVN];

// ---------------- helpers ----------------
__device__ __forceinline__ uint32_t smem_u32(const void* p) {
    uint32_t a;
    asm("{ .reg .u64 t; cvta.to.shared.u64 t, %1; cvt.u32.u64 %0, t; }" : "=r"(a) : "l"(p));
    return a;
}

__device__ __forceinline__ void cp_async16(uint32_t sdst, const void* gsrc) {
    asm volatile("cp.async.cg.shared.global [%0], [%1], 16;" :: "r"(sdst), "l"(gsrc) : "memory");
}
#define CP_COMMIT() asm volatile("cp.async.commit_group;" ::: "memory")
#define CP_WAIT(n)  asm volatile("cp.async.wait_group %0;" :: "n"(n) : "memory")

#define LDSM4(r, addr) \
    asm volatile("ldmatrix.sync.aligned.m8n8.x4.shared.b16 {%0,%1,%2,%3}, [%4];" \
        : "=r"((r)[0]), "=r"((r)[1]), "=r"((r)[2]), "=r"((r)[3]) : "r"(addr))

#define LDSM4T(r, addr) \
    asm volatile("ldmatrix.sync.aligned.m8n8.x4.trans.shared.b16 {%0,%1,%2,%3}, [%4];" \
        : "=r"((r)[0]), "=r"((r)[1]), "=r"((r)[2]), "=r"((r)[3]) : "r"(addr))

#define MMA_BF16(c, a, b0, b1) \
    asm volatile("mma.sync.aligned.m16n8k16.row.col.f32.bf16.bf16.f32 " \
        "{%0,%1,%2,%3}, {%4,%5,%6,%7}, {%8,%9}, {%0,%1,%2,%3};" \
        : "+f"((c)[0]), "+f"((c)[1]), "+f"((c)[2]), "+f"((c)[3]) \
        : "r"((a)[0]), "r"((a)[1]), "r"((a)[2]), "r"((a)[3]), "r"(b0), "r"(b1))

#define MMA_BF16R(c, a0, a1, a2, a3, b0, b1) \
    asm volatile("mma.sync.aligned.m16n8k16.row.col.f32.bf16.bf16.f32 " \
        "{%0,%1,%2,%3}, {%4,%5,%6,%7}, {%8,%9}, {%0,%1,%2,%3};" \
        : "+f"((c)[0]), "+f"((c)[1]), "+f"((c)[2]), "+f"((c)[3]) \
        : "r"(a0), "r"(a1), "r"(a2), "r"(a3), "r"(b0), "r"(b1))

__device__ __forceinline__ void split_bf16(float v, unsigned short& hi, unsigned short& lo) {
    __nv_bfloat16 h = __float2bfloat16(v);
    float r = v - __bfloat162float(h);
    hi = __bfloat16_as_ushort(h);
    lo = __bfloat16_as_ushort(__float2bfloat16(r));
}

// split a pair of floats into packed-bf16 hi2 / lo2 words (low half = first elem)
__device__ __forceinline__ void split2_bf16(float a, float b, uint32_t& hi2, uint32_t& lo2) {
    __nv_bfloat16 ha = __float2bfloat16(a), hb = __float2bfloat16(b);
    float ra = a - __bfloat162float(ha), rb = b - __bfloat162float(hb);
    __nv_bfloat16 la = __float2bfloat16(ra), lb = __float2bfloat16(rb);
    hi2 = (uint32_t)__bfloat16_as_ushort(ha) | ((uint32_t)__bfloat16_as_ushort(hb) << 16);
    lo2 = (uint32_t)__bfloat16_as_ushort(la) | ((uint32_t)__bfloat16_as_ushort(lb) << 16);
}

// ---------------- layernorm -> bf16 hi/lo ----------------
__device__ __forceinline__ float block_sum_256(float v, float* sh) {
    int lane = threadIdx.x & 31, w = threadIdx.x >> 5;
    #pragma unroll
    for (int o = 16; o; o >>= 1) v += __shfl_xor_sync(0xffffffffu, v, o);
    __syncthreads();
    if (lane == 0) sh[w] = v;
    __syncthreads();
    float r = 0.f;
    #pragma unroll
    for (int i = 0; i < 8; i++) r += sh[i];
    return r;
}

__global__ void ln_split_kernel(const float* __restrict__ x, const float* __restrict__ g,
                                const float* __restrict__ b,
                                unsigned short* __restrict__ ohi, unsigned short* __restrict__ olo) {
    __shared__ float sh[8];
    int row = blockIdx.x;
    const float* xr = x + (size_t)row * DIM;
    int t = threadIdx.x;
    float v0[4];
    float s = 0.f;
    #pragma unroll
    for (int u = 0; u < 4; u++) { v0[u] = xr[t + u * 256]; s += v0[u]; }
    s = block_sum_256(s, sh);
    float mean = s * (1.0f / DIM);
    float vs = 0.f;
    #pragma unroll
    for (int u = 0; u < 4; u++) { float d = v0[u] - mean; vs += d * d; }
    vs = block_sum_256(vs, sh);
    float rstd = rsqrtf(vs * (1.0f / DIM) + 1e-5f);
    #pragma unroll
    for (int u = 0; u < 4; u++) {
        int c = t + u * 256;
        float v = (v0[u] - mean) * rstd * g[c] + b[c];
        unsigned short h, l;
        split_bf16(v, h, l);
        ohi[(size_t)row * DIM + c] = h;
        olo[(size_t)row * DIM + c] = l;
    }
}

// ---------------- weight transpose + split ----------------
__global__ void transpose_split_kernel(const float* __restrict__ in, int R, int C,
                                       unsigned short* __restrict__ hi, unsigned short* __restrict__ lo) {
    __shared__ float t[32][33];
    int c0 = blockIdx.x * 32, r0 = blockIdx.y * 32;
    #pragma unroll
    for (int u = 0; u < 4; u++) {
        int r = r0 + threadIdx.y + u * 8;
        t[threadIdx.y + u * 8][threadIdx.x] = in[(size_t)r * C + c0 + threadIdx.x];
    }
    __syncthreads();
    #pragma unroll
    for (int u = 0; u < 4; u++) {
        int c = c0 + threadIdx.y + u * 8;
        float v = t[threadIdx.x][threadIdx.y + u * 8];
        unsigned short h, l;
        split_bf16(v, h, l);
        hi[(size_t)c * R + r0 + threadIdx.x] = h;
        lo[(size_t)c * R + r0 + threadIdx.x] = l;
    }
}

__global__ void concat_bias_kernel(const float* __restrict__ bq, const float* __restrict__ bk,
                                   const float* __restrict__ bv, float* __restrict__ out) {
    int i = blockIdx.x * 256 + threadIdx.x;
    if (i < DIM) out[i] = bq[i];
    else if (i < 2 * DIM) out[i] = bk[i - DIM];
    else if (i < 3 * DIM) out[i] = bv[i - 2 * DIM];
}

// ---------------- mma.sync bf16x3 GEMM, 4-stage pipeline ----------------
// C[M,N] = A[M,K] @ B^T (B stored [N,K]). 128x128 CTA tile, BK=32.
// smem tile: 128 rows x 40 halves (32 data + 8 pad) = 10240 B; 4 stages x 4 tiles.
#define TILEB 10240u
#define GEMM_SMEM (16 * 10240)

__global__ __launch_bounds__(256)
void gemm_mma_kernel(const unsigned short* __restrict__ Ahi, const unsigned short* __restrict__ Alo,
                     const unsigned short* __restrict__ Bhi, const unsigned short* __restrict__ Blo,
                     const float* __restrict__ bias, const float* __restrict__ res,
                     float* __restrict__ outF,
                     unsigned short* __restrict__ outHi, unsigned short* __restrict__ outLo,
                     int N, int K, int gelu) {
    extern __shared__ char smem[];
    const uint32_t sb = smem_u32(smem);
    const int tid  = threadIdx.x;
    const int wid  = tid >> 5;
    const int lane = tid & 31;
    const int wm = wid >> 2;
    const int wn = wid & 3;
    const int bm = blockIdx.y * 128;
    const int bn = blockIdx.x * 128;
    const int g  = lane >> 2;
    const int t4 = lane & 3;

    const uint32_t aOff = (uint32_t)((((lane >> 3) & 1) * 8 + (lane & 7)) * 80 + (lane >> 4) * 16);
    const uint32_t bOff = (uint32_t)(((lane >> 4) * 8 + (lane & 7)) * 80 + ((lane >> 3) & 1) * 16);

    float acc[4][4][4];
    #pragma unroll
    for (int i = 0; i < 4; i++)
        #pragma unroll
        for (int j = 0; j < 4; j++)
            #pragma unroll
            for (int q = 0; q < 4; q++) acc[i][j][q] = 0.f;

    const int NCH = K >> 5;
    const unsigned short* gsrc[4] = {Ahi, Alo, Bhi, Blo};
    const int rbase[4] = {bm, bm, bn, bn};

    auto load_chunk = [&](int stage, int k0) {
        #pragma unroll
        for (int t = 0; t < 4; t++) {
            uint32_t dst = sb + (uint32_t)(stage * 4 + t) * TILEB;
            const unsigned short* gp = gsrc[t];
            #pragma unroll
            for (int u = 0; u < 2; u++) {
                int idx = tid + 256 * u;
                int r = idx >> 2;
                int cc = idx & 3;
                cp_async16(dst + (uint32_t)(r * 80 + cc * 16),
                           gp + (size_t)(rbase[t] + r) * K + k0 + cc * 8);
            }
        }
        CP_COMMIT();
    };

    load_chunk(0, 0);
    load_chunk(1, 32);
    load_chunk(2, 64);
    load_chunk(3, 96);

    for (int i = 0; i < NCH; i++) {
        CP_WAIT(3);
        __syncthreads();

        const uint32_t base = sb + (uint32_t)((i & 3) * 4) * TILEB;
        const uint32_t aHiB = base,            aLoB = base + TILEB;
        const uint32_t bHiB = base + 2*TILEB,  bLoB = base + 3*TILEB;

        #pragma unroll
        for (int ks = 0; ks < 2; ks++) {
            uint32_t bh[2][4], bl[2][4];
            #pragma unroll
            for (int np = 0; np < 2; np++) {
                uint32_t o = (uint32_t)((wn * 32 + np * 16) * 80 + ks * 32) + bOff;
                LDSM4(bh[np], bHiB + o);
                LDSM4(bl[np], bLoB + o);
            }
            #pragma unroll
            for (int mt = 0; mt < 4; mt++) {
                uint32_t ah[4], al[4];
                uint32_t o = (uint32_t)((wm * 64 + mt * 16) * 80 + ks * 32) + aOff;
                LDSM4(ah, aHiB + o);
                LDSM4(al, aLoB + o);
                #pragma unroll
                for (int nt = 0; nt < 4; nt++) {
                    int np = nt >> 1, sub = (nt & 1) * 2;
                    uint32_t b0h = bh[np][sub], b1h = bh[np][sub + 1];
                    uint32_t b0l = bl[np][sub], b1l = bl[np][sub + 1];
                    MMA_BF16(acc[mt][nt], ah, b0h, b1h);
                    MMA_BF16(acc[mt][nt], ah, b0l, b1l);
                    MMA_BF16(acc[mt][nt], al, b0h, b1h);
                }
            }
        }
        __syncthreads();

        if (i + 4 < NCH) load_chunk(i & 3, (i + 4) * 32);
        else             CP_COMMIT();   // keep group count in lockstep
    }

    // --- epilogue ---
    #pragma unroll
    for (int mt = 0; mt < 4; mt++) {
        int r0 = bm + wm * 64 + mt * 16 + g;
        #pragma unroll
        for (int nt = 0; nt < 4; nt++) {
            int c = bn + wn * 32 + nt * 8 + t4 * 2;
            float v[4];
            v[0] = acc[mt][nt][0] + bias[c];
            v[1] = acc[mt][nt][1] + bias[c + 1];
            v[2] = acc[mt][nt][2] + bias[c];
            v[3] = acc[mt][nt][3] + bias[c + 1];
            if (gelu) {
                #pragma unroll
                for (int q = 0; q < 4; q++)
                    v[q] = 0.5f * v[q] * (1.0f + erff(v[q] * 0.70710678118654752f));
            }
            if (res) {
                v[0] += res[(size_t)r0 * N + c];
                v[1] += res[(size_t)r0 * N + c + 1];
                v[2] += res[(size_t)(r0 + 8) * N + c];
                v[3] += res[(size_t)(r0 + 8) * N + c + 1];
            }
            if (outF) {
                *(float2*)(outF + (size_t)r0 * N + c)       = make_float2(v[0], v[1]);
                *(float2*)(outF + (size_t)(r0 + 8) * N + c) = make_float2(v[2], v[3]);
            } else {
                uint32_t h2, l2;
                split2_bf16(v[0], v[1], h2, l2);
                *(uint32_t*)(outHi + (size_t)r0 * N + c) = h2;
                *(uint32_t*)(outLo + (size_t)r0 * N + c) = l2;
                split2_bf16(v[2], v[3], h2, l2);
                *(uint32_t*)(outHi + (size_t)(r0 + 8) * N + c) = h2;
                *(uint32_t*)(outLo + (size_t)(r0 + 8) * N + c) = l2;
            }
        }
    }
}

// ---------------- flash attention, mma.sync bf16x3 ----------------
// 64 q-rows per block, 4 warps (warp w -> rows 16w..16w+15), 2-stage K/V pipeline.
// smem row stride: 72 halves (64 data + 8 pad) = 144 B.
#define ATILE 9216u                     // 64 * 144
#define ATT_SMEM (2 * 4 * 9216)         // 2 stages x (Khi,Klo,Vhi,Vlo)

__global__ __launch_bounds__(128)
void attn_mma_kernel(const unsigned short* __restrict__ qkvhi,
                     const unsigned short* __restrict__ qkvlo,
                     unsigned short* __restrict__ Ohi, unsigned short* __restrict__ Olo) {
    extern __shared__ char smem[];
    const uint32_t sb = smem_u32(smem);
    const int h  = blockIdx.y;
    const int q0 = blockIdx.x * 64;
    const int tid = threadIdx.x;
    const int w = tid >> 5, lane = tid & 31;
    const int g = lane >> 2, t4 = lane & 3;
    const int qcol = h * HDK, kcol = DIM + h * HDK, vcol = 2 * DIM + h * HDK;

    const uint32_t aOff = (uint32_t)((((lane >> 3) & 1) * 8 + (lane & 7)) * 144 + (lane >> 4) * 16);
    const uint32_t bOff = (uint32_t)(((lane >> 4) * 8 + (lane & 7)) * 144 + ((lane >> 3) & 1) * 16);
    const uint32_t vOff = (uint32_t)((lane & 15) * 144 + (lane >> 4) * 16);

    #define AKHI(s) (sb + (uint32_t)(s) * 4u * ATILE)
    #define AKLO(s) (AKHI(s) + ATILE)
    #define AVHI(s) (AKHI(s) + 2u * ATILE)
    #define AVLO(s) (AKHI(s) + 3u * ATILE)

    // ---- stage Q through smem into registers ----
    #pragma unroll
    for (int u = 0; u < 4; u++) {
        int idx = tid + u * 128;
        int row = idx >> 3, c16 = idx & 7;
        uint32_t off = (uint32_t)(row * 144 + c16 * 16);
        size_t gq = (size_t)(q0 + row) * QKVN + qcol + c16 * 8;
        cp_async16(AKHI(0) + off, qkvhi + gq);
        cp_async16(AKLO(0) + off, qkvlo + gq);
    }
    CP_COMMIT(); CP_WAIT(0); __syncthreads();

    uint32_t qh[4][4], ql[4][4];
    #pragma unroll
    for (int ks = 0; ks < 4; ks++) {
        uint32_t o = (uint32_t)(w * 16 * 144 + ks * 32);
        LDSM4(qh[ks], AKHI(0) + o + aOff);
        LDSM4(ql[ks], AKLO(0) + o + aOff);
    }
    __syncthreads();

    auto load_kv = [&](int st, int kt) {
        #pragma unroll
        for (int u = 0; u < 4; u++) {
            int idx = tid + u * 128;
            int row = idx >> 3, c16 = idx & 7;
            uint32_t off = (uint32_t)(row * 144 + c16 * 16);
            size_t gk = (size_t)(kt + row) * QKVN + kcol + c16 * 8;
            size_t gv = (size_t)(kt + row) * QKVN + vcol + c16 * 8;
            cp_async16(AKHI(st) + off, qkvhi + gk);
            cp_async16(AKLO(st) + off, qkvlo + gk);
            cp_async16(AVHI(st) + off, qkvhi + gv);
            cp_async16(AVLO(st) + off, qkvlo + gv);
        }
        CP_COMMIT();
    };
    load_kv(0, 0);
    load_kv(1, 64);

    float of[8][4];
    #pragma unroll
    for (int j = 0; j < 8; j++)
        #pragma unroll
        for (int q = 0; q < 4; q++) of[j][q] = 0.f;
    float m0 = -1e30f, m1 = -1e30f, l0 = 0.f, l1 = 0.f;

    for (int it = 0; it < SQ / 64; it++) {
        CP_WAIT(1);
        __syncthreads();
        const int st = it & 1;

        // ---- S = (Q @ K^T), bf16x3 ----
        float sf[8][4];
        #pragma unroll
        for (int j = 0; j < 8; j++)
            #pragma unroll
            for (int q = 0; q < 4; q++) sf[j][q] = 0.f;

        #pragma unroll
        for (int ks = 0; ks < 4; ks++) {
            #pragma unroll
            for (int nb = 0; nb < 4; nb++) {
                uint32_t kh[4], kl[4];
                uint32_t o = (uint32_t)(nb * 16 * 144 + ks * 32);
                LDSM4(kh, AKHI(st) + o + bOff);
                LDSM4(kl, AKLO(st) + o + bOff);
                MMA_BF16(sf[2*nb],   qh[ks], kh[0], kh[1]);
                MMA_BF16(sf[2*nb+1], qh[ks], kh[2], kh[3]);
                MMA_BF16(sf[2*nb],   qh[ks], kl[0], kl[1]);
                MMA_BF16(sf[2*nb+1], qh[ks], kl[2], kl[3]);
                MMA_BF16(sf[2*nb],   ql[ks], kh[0], kh[1]);
                MMA_BF16(sf[2*nb+1], ql[ks], kh[2], kh[3]);
            }
        }

        // ---- online softmax (rows g and g+8; reduce across t4 quads) ----
        float mx0 = -1e30f, mx1 = -1e30f;
        #pragma unroll
        for (int j = 0; j < 8; j++) {
            #pragma unroll
            for (int q = 0; q < 4; q++) sf[j][q] *= 0.125f;
            mx0 = fmaxf(mx0, fmaxf(sf[j][0], sf[j][1]));
            mx1 = fmaxf(mx1, fmaxf(sf[j][2], sf[j][3]));
        }
        mx0 = fmaxf(mx0, __shfl_xor_sync(0xffffffffu, mx0, 1));
        mx0 = fmaxf(mx0, __shfl_xor_sync(0xffffffffu, mx0, 2));
        mx1 = fmaxf(mx1, __shfl_xor_sync(0xffffffffu, mx1, 1));
        mx1 = fmaxf(mx1, __shfl_xor_sync(0xffffffffu, mx1, 2));
        float mn0 = fmaxf(m0, mx0), mn1 = fmaxf(m1, mx1);
        float sc0 = __expf(m0 - mn0), sc1 = __expf(m1 - mn1);
        m0 = mn0; m1 = mn1;
        float s0 = 0.f, s1 = 0.f;
        #pragma unroll
        for (int j = 0; j < 8; j++) {
            sf[j][0] = __expf(sf[j][0] - mn0); s0 += sf[j][0];
            sf[j][1] = __expf(sf[j][1] - mn0); s0 += sf[j][1];
            sf[j][2] = __expf(sf[j][2] - mn1); s1 += sf[j][2];
            sf[j][3] = __expf(sf[j][3] - mn1); s1 += sf[j][3];
        }
        s0 += __shfl_xor_sync(0xffffffffu, s0, 1);
        s0 += __shfl_xor_sync(0xffffffffu, s0, 2);
        s1 += __shfl_xor_sync(0xffffffffu, s1, 1);
        s1 += __shfl_xor_sync(0xffffffffu, s1, 2);
        l0 = l0 * sc0 + s0;
        l1 = l1 * sc1 + s1;
        #pragma unroll
        for (int j = 0; j < 8; j++) {
            of[j][0] *= sc0; of[j][1] *= sc0;
            of[j][2] *= sc1; of[j][3] *= sc1;
        }

        // ---- O += P @ V, bf16x3 (P re-packed from fragments) ----
        #pragma unroll
        for (int jp = 0; jp < 4; jp++) {
            uint32_t ph0, ph1, ph2, ph3, pl0, pl1, pl2, pl3;
            split2_bf16(sf[2*jp][0],   sf[2*jp][1],   ph0, pl0);
            split2_bf16(sf[2*jp][2],   sf[2*jp][3],   ph1, pl1);
            split2_bf16(sf[2*jp+1][0], sf[2*jp+1][1], ph2, pl2);
            split2_bf16(sf[2*jp+1][2], sf[2*jp+1][3], ph3, pl3);
            #pragma unroll
            for (int nb = 0; nb < 4; nb++) {
                uint32_t vh[4], vl[4];
                uint32_t o = (uint32_t)(jp * 16 * 144 + nb * 16 * 2);
                LDSM4T(vh, AVHI(st) + o + vOff);
                LDSM4T(vl, AVLO(st) + o + vOff);
                MMA_BF16R(of[2*nb],   ph0, ph1, ph2, ph3, vh[0], vh[1]);
                MMA_BF16R(of[2*nb+1], ph0, ph1, ph2, ph3, vh[2], vh[3]);
                MMA_BF16R(of[2*nb],   ph0, ph1, ph2, ph3, vl[0], vl[1]);
                MMA_BF16R(of[2*nb+1], ph0, ph1, ph2, ph3, vl[2], vl[3]);
                MMA_BF16R(of[2*nb],   pl0, pl1, pl2, pl3, vh[0], vh[1]);
                MMA_BF16R(of[2*nb+1], pl0, pl1, pl2, pl3, vh[2], vh[3]);
            }
        }

        __syncthreads();
        if (it + 2 < SQ / 64) load_kv(st, (it + 2) * 64);
        else                  CP_COMMIT();
    }

    // ---- write O / l, [H,S,DK] hi/lo ----
    float inv0 = 1.0f / l0, inv1 = 1.0f / l1;
    int r0 = q0 + w * 16 + g;
    #pragma unroll
    for (int j = 0; j < 8; j++) {
        int d = 8 * j + 2 * t4;
        uint32_t h2, l2;
        split2_bf16(of[j][0] * inv0, of[j][1] * inv0, h2, l2);
        *(uint32_t*)(Ohi + (size_t)h * SQ * HDK + (size_t)r0 * HDK + d) = h2;
        *(uint32_t*)(Olo + (size_t)h * SQ * HDK + (size_t)r0 * HDK + d) = l2;
        split2_bf16(of[j][2] * inv1, of[j][3] * inv1, h2, l2);
        *(uint32_t*)(Ohi + (size_t)h * SQ * HDK + (size_t)(r0 + 8) * HDK + d) = h2;
        *(uint32_t*)(Olo + (size_t)h * SQ * HDK + (size_t)(r0 + 8) * HDK + d) = l2;
    }
}

// ---------------- launch ----------------
extern "C" void kernel_launch(void* const* d_in, const int* in_sizes, int n_in,
                              void* d_out, int out_size) {
    const float* x     = (const float*)d_in[0];
    const float* wq    = (const float*)d_in[1];
    const float* bq    = (const float*)d_in[2];
    const float* wk    = (const float*)d_in[3];
    const float* bk    = (const float*)d_in[4];
    const float* wv    = (const float*)d_in[5];
    const float* bv    = (const float*)d_in[6];
    const float* wo    = (const float*)d_in[7];
    const float* bo    = (const float*)d_in[8];
    const float* w1    = (const float*)d_in[9];
    const float* b1    = (const float*)d_in[10];
    const float* w2    = (const float*)d_in[11];
    const float* b2    = (const float*)d_in[12];
    const float* ln1_g = (const float*)d_in[13];
    const float* ln1_b = (const float*)d_in[14];
    const float* ln2_g = (const float*)d_in[15];
    const float* ln2_b = (const float*)d_in[16];
    float* out = (float*)d_out;

    unsigned short *hhi, *hlo, *qkvh, *qkvl, *aohi, *aolo, *fhi, *flo;
    unsigned short *wqkvh, *wqkvl, *woh, *wol, *w1h, *w1l, *w2h, *w2l;
    float *x1, *bqkv;
    cudaGetSymbolAddress((void**)&hhi,  g_h_hi);  cudaGetSymbolAddress((void**)&hlo,  g_h_lo);
    cudaGetSymbolAddress((void**)&qkvh, g_qkv_hi); cudaGetSymbolAddress((void**)&qkvl, g_qkv_lo);
    cudaGetSymbolAddress((void**)&aohi, g_ao_hi); cudaGetSymbolAddress((void**)&aolo, g_ao_lo);
    cudaGetSymbolAddress((void**)&x1,   g_x1);
    cudaGetSymbolAddress((void**)&fhi,  g_f_hi);  cudaGetSymbolAddress((void**)&flo,  g_f_lo);
    cudaGetSymbolAddress((void**)&wqkvh, g_wqkv_hi); cudaGetSymbolAddress((void**)&wqkvl, g_wqkv_lo);
    cudaGetSymbolAddress((void**)&woh,  g_wo_hi); cudaGetSymbolAddress((void**)&wol,  g_wo_lo);
    cudaGetSymbolAddress((void**)&w1h,  g_w1_hi); cudaGetSymbolAddress((void**)&w1l,  g_w1_lo);
    cudaGetSymbolAddress((void**)&w2h,  g_w2_hi); cudaGetSymbolAddress((void**)&w2l,  g_w2_lo);
    cudaGetSymbolAddress((void**)&bqkv, g_bqkv);

    cudaFuncSetAttribute(gemm_mma_kernel,
                         cudaFuncAttributeMaxDynamicSharedMemorySize, GEMM_SMEM);
    cudaFuncSetAttribute(attn_mma_kernel,
                         cudaFuncAttributeMaxDynamicSharedMemorySize, ATT_SMEM);

    dim3 tb(32, 8);

    // weight prep (transpose + bf16 split)
    transpose_split_kernel<<<dim3(DIM/32,  DIM/32),  tb>>>(wq, DIM,  DIM,  wqkvh,             wqkvl);
    transpose_split_kernel<<<dim3(DIM/32,  DIM/32),  tb>>>(wk, DIM,  DIM,  wqkvh + DIM*DIM,   wqkvl + DIM*DIM);
    transpose_split_kernel<<<dim3(DIM/32,  DIM/32),  tb>>>(wv, DIM,  DIM,  wqkvh + 2*DIM*DIM, wqkvl + 2*DIM*DIM);
    transpose_split_kernel<<<dim3(DIM/32,  DIM/32),  tb>>>(wo, DIM,  DIM,  woh, wol);
    transpose_split_kernel<<<dim3(MLPD/32, DIM/32),  tb>>>(w1, DIM,  MLPD, w1h, w1l);
    transpose_split_kernel<<<dim3(DIM/32,  MLPD/32), tb>>>(w2, MLPD, DIM,  w2h, w2l);
    concat_bias_kernel<<<QKVN/256, 256>>>(bq, bk, bv, bqkv);

    // LN1 -> split
    ln_split_kernel<<<SQ, 256>>>(x, ln1_g, ln1_b, hhi, hlo);

    // QKV fused GEMM -> bf16 hi/lo
    gemm_mma_kernel<<<dim3(QKVN/128, SQ/128), 256, GEMM_SMEM>>>(
        hhi, hlo, wqkvh, wqkvl, bqkv, nullptr, nullptr, qkvh, qkvl, QKVN, DIM, 0);

    // attention (tensor core) -> ao hi/lo
    attn_mma_kernel<<<dim3(SQ/64, NH), 128, ATT_SMEM>>>(qkvh, qkvl, aohi, aolo);

    // O-proj + residual(x) -> x1 fp32
    gemm_mma_kernel<<<dim3(DIM/128, SQ/128), 256, GEMM_SMEM>>>(
        aohi, aolo, woh, wol, bo, x, x1, nullptr, nullptr, DIM, DIM, 0);

    // LN2 -> split
    ln_split_kernel<<<SQ, 256>>>(x1, ln2_g, ln2_b, hhi, hlo);

    // FFN1 + GELU -> f hi/lo
    gemm_mma_kernel<<<dim3(MLPD/128, SQ/128), 256, GEMM_SMEM>>>(
        hhi, hlo, w1h, w1l, b1, nullptr, nullptr, fhi, flo, MLPD, DIM, 1);

    // FFN2 + residual(x1) -> out fp32
    gemm_mma_kernel<<<dim3(DIM/128, SQ/128), 256, GEMM_SMEM>>>(
        fhi, flo, w2h, w2l, b2, x1, out, nullptr, nullptr, DIM, MLPD, 0);
}

// round 5
// speedup vs baseline: 3.0317x; 1.0008x over previous
#include <cuda_runtime.h>
#include <cuda_bf16.h>
#include <math.h>
#include <stdint.h>

#define SQ   2048
#define DIM  1024
#define NH   16
#define HDK  64
#define MLPD 4096
#define QKVN 3072

// ---------------- scratch (no allocations allowed) ----------------
__device__ unsigned short g_h_hi [SQ*DIM],  g_h_lo [SQ*DIM];
__device__ unsigned short g_qkv_hi[SQ*QKVN], g_qkv_lo[SQ*QKVN];
__device__ unsigned short g_ao_hi[SQ*DIM],  g_ao_lo[SQ*DIM];
__device__ float          g_x1   [SQ*DIM];
__device__ unsigned short g_f_hi [SQ*MLPD], g_f_lo [SQ*MLPD];
__device__ unsigned short g_wqkv_hi[QKVN*DIM], g_wqkv_lo[QKVN*DIM];
__device__ unsigned short g_wo_hi [DIM*DIM],   g_wo_lo [DIM*DIM];
__device__ unsigned short g_w1_hi [MLPD*DIM],  g_w1_lo [MLPD*DIM];
__device__ unsigned short g_w2_hi [DIM*MLPD],  g_w2_lo [DIM*MLPD];
__device__ float          g_bqkv[QKVN];

// ---------------- helpers ----------------
__device__ __forceinline__ uint32_t smem_u32(const void* p) {
    uint32_t a;
    asm("{ .reg .u64 t; cvta.to.shared.u64 t, %1; cvt.u32.u64 %0, t; }" : "=r"(a) : "l"(p));
    return a;
}

__device__ __forceinline__ void cp_async16(uint32_t sdst, const void* gsrc) {
    asm volatile("cp.async.cg.shared.global [%0], [%1], 16;" :: "r"(sdst), "l"(gsrc) : "memory");
}
#define CP_COMMIT() asm volatile("cp.async.commit_group;" ::: "memory")
#define CP_WAIT(n)  asm volatile("cp.async.wait_group %0;" :: "n"(n) : "memory")

#define LDSM4(r, addr) \
    asm volatile("ldmatrix.sync.aligned.m8n8.x4.shared.b16 {%0,%1,%2,%3}, [%4];" \
        : "=r"((r)[0]), "=r"((r)[1]), "=r"((r)[2]), "=r"((r)[3]) : "r"(addr))

#define LDSM4T(r, addr) \
    asm volatile("ldmatrix.sync.aligned.m8n8.x4.trans.shared.b16 {%0,%1,%2,%3}, [%4];" \
        : "=r"((r)[0]), "=r"((r)[1]), "=r"((r)[2]), "=r"((r)[3]) : "r"(addr))

#define MMA_BF16(c, a, b0, b1) \
    asm volatile("mma.sync.aligned.m16n8k16.row.col.f32.bf16.bf16.f32 " \
        "{%0,%1,%2,%3}, {%4,%5,%6,%7}, {%8,%9}, {%0,%1,%2,%3};" \
        : "+f"((c)[0]), "+f"((c)[1]), "+f"((c)[2]), "+f"((c)[3]) \
        : "r"((a)[0]), "r"((a)[1]), "r"((a)[2]), "r"((a)[3]), "r"(b0), "r"(b1))

#define MMA_BF16R(c, a0, a1, a2, a3, b0, b1) \
    asm volatile("mma.sync.aligned.m16n8k16.row.col.f32.bf16.bf16.f32 " \
        "{%0,%1,%2,%3}, {%4,%5,%6,%7}, {%8,%9}, {%0,%1,%2,%3};" \
        : "+f"((c)[0]), "+f"((c)[1]), "+f"((c)[2]), "+f"((c)[3]) \
        : "r"(a0), "r"(a1), "r"(a2), "r"(a3), "r"(b0), "r"(b1))

__device__ __forceinline__ void split_bf16(float v, unsigned short& hi, unsigned short& lo) {
    __nv_bfloat16 h = __float2bfloat16(v);
    float r = v - __bfloat162float(h);
    hi = __bfloat16_as_ushort(h);
    lo = __bfloat16_as_ushort(__float2bfloat16(r));
}

__device__ __forceinline__ void split2_bf16(float a, float b, uint32_t& hi2, uint32_t& lo2) {
    __nv_bfloat16 ha = __float2bfloat16(a), hb = __float2bfloat16(b);
    float ra = a - __bfloat162float(ha), rb = b - __bfloat162float(hb);
    __nv_bfloat16 la = __float2bfloat16(ra), lb = __float2bfloat16(rb);
    hi2 = (uint32_t)__bfloat16_as_ushort(ha) | ((uint32_t)__bfloat16_as_ushort(hb) << 16);
    lo2 = (uint32_t)__bfloat16_as_ushort(la) | ((uint32_t)__bfloat16_as_ushort(lb) << 16);
}

// ---------------- layernorm -> bf16 hi/lo ----------------
__device__ __forceinline__ float block_sum_256(float v, float* sh) {
    int lane = threadIdx.x & 31, w = threadIdx.x >> 5;
    #pragma unroll
    for (int o = 16; o; o >>= 1) v += __shfl_xor_sync(0xffffffffu, v, o);
    __syncthreads();
    if (lane == 0) sh[w] = v;
    __syncthreads();
    float r = 0.f;
    #pragma unroll
    for (int i = 0; i < 8; i++) r += sh[i];
    return r;
}

__global__ void ln_split_kernel(const float* __restrict__ x, const float* __restrict__ g,
                                const float* __restrict__ b,
                                unsigned short* __restrict__ ohi, unsigned short* __restrict__ olo) {
    __shared__ float sh[8];
    int row = blockIdx.x;
    const float* xr = x + (size_t)row * DIM;
    int t = threadIdx.x;
    float v0[4];
    float s = 0.f;
    #pragma unroll
    for (int u = 0; u < 4; u++) { v0[u] = xr[t + u * 256]; s += v0[u]; }
    s = block_sum_256(s, sh);
    float mean = s * (1.0f / DIM);
    float vs = 0.f;
    #pragma unroll
    for (int u = 0; u < 4; u++) { float d = v0[u] - mean; vs += d * d; }
    vs = block_sum_256(vs, sh);
    float rstd = rsqrtf(vs * (1.0f / DIM) + 1e-5f);
    #pragma unroll
    for (int u = 0; u < 4; u++) {
        int c = t + u * 256;
        float v = (v0[u] - mean) * rstd * g[c] + b[c];
        unsigned short h, l;
        split_bf16(v, h, l);
        ohi[(size_t)row * DIM + c] = h;
        olo[(size_t)row * DIM + c] = l;
    }
}

// ---------------- weight transpose + split ----------------
__global__ void transpose_split_kernel(const float* __restrict__ in, int R, int C,
                                       unsigned short* __restrict__ hi, unsigned short* __restrict__ lo) {
    __shared__ float t[32][33];
    int c0 = blockIdx.x * 32, r0 = blockIdx.y * 32;
    #pragma unroll
    for (int u = 0; u < 4; u++) {
        int r = r0 + threadIdx.y + u * 8;
        t[threadIdx.y + u * 8][threadIdx.x] = in[(size_t)r * C + c0 + threadIdx.x];
    }
    __syncthreads();
    #pragma unroll
    for (int u = 0; u < 4; u++) {
        int c = c0 + threadIdx.y + u * 8;
        float v = t[threadIdx.x][threadIdx.y + u * 8];
        unsigned short h, l;
        split_bf16(v, h, l);
        hi[(size_t)c * R + r0 + threadIdx.x] = h;
        lo[(size_t)c * R + r0 + threadIdx.x] = l;
    }
}

// merged q/k/v transpose: z selects source, writes into wqkv[z*DIM*DIM ...]
__global__ void transpose_qkv_kernel(const float* __restrict__ wq, const float* __restrict__ wk,
                                     const float* __restrict__ wv,
                                     unsigned short* __restrict__ hi, unsigned short* __restrict__ lo) {
    __shared__ float t[32][33];
    const float* in = (blockIdx.z == 0) ? wq : (blockIdx.z == 1) ? wk : wv;
    unsigned short* hiz = hi + (size_t)blockIdx.z * DIM * DIM;
    unsigned short* loz = lo + (size_t)blockIdx.z * DIM * DIM;
    int c0 = blockIdx.x * 32, r0 = blockIdx.y * 32;
    #pragma unroll
    for (int u = 0; u < 4; u++) {
        int r = r0 + threadIdx.y + u * 8;
        t[threadIdx.y + u * 8][threadIdx.x] = in[(size_t)r * DIM + c0 + threadIdx.x];
    }
    __syncthreads();
    #pragma unroll
    for (int u = 0; u < 4; u++) {
        int c = c0 + threadIdx.y + u * 8;
        float v = t[threadIdx.x][threadIdx.y + u * 8];
        unsigned short h, l;
        split_bf16(v, h, l);
        hiz[(size_t)c * DIM + r0 + threadIdx.x] = h;
        loz[(size_t)c * DIM + r0 + threadIdx.x] = l;
    }
}

__global__ void concat_bias_kernel(const float* __restrict__ bq, const float* __restrict__ bk,
                                   const float* __restrict__ bv, float* __restrict__ out) {
    int i = blockIdx.x * 256 + threadIdx.x;
    if (i < DIM) out[i] = bq[i];
    else if (i < 2 * DIM) out[i] = bk[i - DIM];
    else if (i < 3 * DIM) out[i] = bv[i - 2 * DIM];
}

// ---------------- mma.sync bf16x3 GEMM, 5-stage pipeline ----------------
#define TILEB 10240u
#define STAGES 5
#define GEMM_SMEM (STAGES * 4 * 10240)

__global__ __launch_bounds__(256)
void gemm_mma_kernel(const unsigned short* __restrict__ Ahi, const unsigned short* __restrict__ Alo,
                     const unsigned short* __restrict__ Bhi, const unsigned short* __restrict__ Blo,
                     const float* __restrict__ bias, const float* __restrict__ res,
                     float* __restrict__ outF,
                     unsigned short* __restrict__ outHi, unsigned short* __restrict__ outLo,
                     int N, int K, int gelu) {
    extern __shared__ char smem[];
    const uint32_t sb = smem_u32(smem);
    const int tid  = threadIdx.x;
    const int wid  = tid >> 5;
    const int lane = tid & 31;
    const int wm = wid >> 2;
    const int wn = wid & 3;
    const int bm = blockIdx.y * 128;
    const int bn = blockIdx.x * 128;
    const int g  = lane >> 2;
    const int t4 = lane & 3;

    const uint32_t aOff = (uint32_t)((((lane >> 3) & 1) * 8 + (lane & 7)) * 80 + (lane >> 4) * 16);
    const uint32_t bOff = (uint32_t)(((lane >> 4) * 8 + (lane & 7)) * 80 + ((lane >> 3) & 1) * 16);

    float acc[4][4][4];
    #pragma unroll
    for (int i = 0; i < 4; i++)
        #pragma unroll
        for (int j = 0; j < 4; j++)
            #pragma unroll
            for (int q = 0; q < 4; q++) acc[i][j][q] = 0.f;

    const int NCH = K >> 5;
    const unsigned short* gsrc[4] = {Ahi, Alo, Bhi, Blo};
    const int rbase[4] = {bm, bm, bn, bn};

    auto load_chunk = [&](int stage, int k0) {
        #pragma unroll
        for (int t = 0; t < 4; t++) {
            uint32_t dst = sb + (uint32_t)(stage * 4 + t) * TILEB;
            const unsigned short* gp = gsrc[t];
            #pragma unroll
            for (int u = 0; u < 2; u++) {
                int idx = tid + 256 * u;
                int r = idx >> 2;
                int cc = idx & 3;
                cp_async16(dst + (uint32_t)(r * 80 + cc * 16),
                           gp + (size_t)(rbase[t] + r) * K + k0 + cc * 8);
            }
        }
        CP_COMMIT();
    };

    #pragma unroll
    for (int s = 0; s < STAGES; s++) load_chunk(s, s * 32);

    int st = 0;
    for (int i = 0; i < NCH; i++) {
        CP_WAIT(STAGES - 1);
        __syncthreads();

        const uint32_t base = sb + (uint32_t)(st * 4) * TILEB;
        const uint32_t aHiB = base,            aLoB = base + TILEB;
        const uint32_t bHiB = base + 2*TILEB,  bLoB = base + 3*TILEB;

        #pragma unroll
        for (int ks = 0; ks < 2; ks++) {
            uint32_t bh[2][4], bl[2][4];
            #pragma unroll
            for (int np = 0; np < 2; np++) {
                uint32_t o = (uint32_t)((wn * 32 + np * 16) * 80 + ks * 32) + bOff;
                LDSM4(bh[np], bHiB + o);
                LDSM4(bl[np], bLoB + o);
            }
            #pragma unroll
            for (int mt = 0; mt < 4; mt++) {
                uint32_t ah[4], al[4];
                uint32_t o = (uint32_t)((wm * 64 + mt * 16) * 80 + ks * 32) + aOff;
                LDSM4(ah, aHiB + o);
                LDSM4(al, aLoB + o);
                #pragma unroll
                for (int nt = 0; nt < 4; nt++) {
                    int np = nt >> 1, sub = (nt & 1) * 2;
                    uint32_t b0h = bh[np][sub], b1h = bh[np][sub + 1];
                    uint32_t b0l = bl[np][sub], b1l = bl[np][sub + 1];
                    MMA_BF16(acc[mt][nt], ah, b0h, b1h);
                    MMA_BF16(acc[mt][nt], ah, b0l, b1l);
                    MMA_BF16(acc[mt][nt], al, b0h, b1h);
                }
            }
        }
        __syncthreads();

        if (i + STAGES < NCH) load_chunk(st, (i + STAGES) * 32);
        else                  CP_COMMIT();
        st = (st + 1 == STAGES) ? 0 : st + 1;
    }

    // --- epilogue ---
    #pragma unroll
    for (int mt = 0; mt < 4; mt++) {
        int r0 = bm + wm * 64 + mt * 16 + g;
        #pragma unroll
        for (int nt = 0; nt < 4; nt++) {
            int c = bn + wn * 32 + nt * 8 + t4 * 2;
            float v[4];
            v[0] = acc[mt][nt][0] + bias[c];
            v[1] = acc[mt][nt][1] + bias[c + 1];
            v[2] = acc[mt][nt][2] + bias[c];
            v[3] = acc[mt][nt][3] + bias[c + 1];
            if (gelu) {
                #pragma unroll
                for (int q = 0; q < 4; q++)
                    v[q] = 0.5f * v[q] * (1.0f + erff(v[q] * 0.70710678118654752f));
            }
            if (res) {
                v[0] += res[(size_t)r0 * N + c];
                v[1] += res[(size_t)r0 * N + c + 1];
                v[2] += res[(size_t)(r0 + 8) * N + c];
                v[3] += res[(size_t)(r0 + 8) * N + c + 1];
            }
            if (outF) {
                *(float2*)(outF + (size_t)r0 * N + c)       = make_float2(v[0], v[1]);
                *(float2*)(outF + (size_t)(r0 + 8) * N + c) = make_float2(v[2], v[3]);
            } else {
                uint32_t h2, l2;
                split2_bf16(v[0], v[1], h2, l2);
                *(uint32_t*)(outHi + (size_t)r0 * N + c) = h2;
                *(uint32_t*)(outLo + (size_t)r0 * N + c) = l2;
                split2_bf16(v[2], v[3], h2, l2);
                *(uint32_t*)(outHi + (size_t)(r0 + 8) * N + c) = h2;
                *(uint32_t*)(outLo + (size_t)(r0 + 8) * N + c) = l2;
            }
        }
    }
}

// ---------------- flash attention, mma.sync bf16x3 ----------------
#define ATILE 9216u
#define ATT_SMEM (2 * 4 * 9216)

__global__ __launch_bounds__(128)
void attn_mma_kernel(const unsigned short* __restrict__ qkvhi,
                     const unsigned short* __restrict__ qkvlo,
                     unsigned short* __restrict__ Ohi, unsigned short* __restrict__ Olo) {
    extern __shared__ char smem[];
    const uint32_t sb = smem_u32(smem);
    const int h  = blockIdx.y;
    const int q0 = blockIdx.x * 64;
    const int tid = threadIdx.x;
    const int w = tid >> 5, lane = tid & 31;
    const int g = lane >> 2, t4 = lane & 3;
    const int qcol = h * HDK, kcol = DIM + h * HDK, vcol = 2 * DIM + h * HDK;

    const uint32_t aOff = (uint32_t)((((lane >> 3) & 1) * 8 + (lane & 7)) * 144 + (lane >> 4) * 16);
    const uint32_t bOff = (uint32_t)(((lane >> 4) * 8 + (lane & 7)) * 144 + ((lane >> 3) & 1) * 16);
    const uint32_t vOff = (uint32_t)((lane & 15) * 144 + (lane >> 4) * 16);

    #define AKHI(s) (sb + (uint32_t)(s) * 4u * ATILE)
    #define AKLO(s) (AKHI(s) + ATILE)
    #define AVHI(s) (AKHI(s) + 2u * ATILE)
    #define AVLO(s) (AKHI(s) + 3u * ATILE)

    #pragma unroll
    for (int u = 0; u < 4; u++) {
        int idx = tid + u * 128;
        int row = idx >> 3, c16 = idx & 7;
        uint32_t off = (uint32_t)(row * 144 + c16 * 16);
        size_t gq = (size_t)(q0 + row) * QKVN + qcol + c16 * 8;
        cp_async16(AKHI(0) + off, qkvhi + gq);
        cp_async16(AKLO(0) + off, qkvlo + gq);
    }
    CP_COMMIT(); CP_WAIT(0); __syncthreads();

    uint32_t qh[4][4], ql[4][4];
    #pragma unroll
    for (int ks = 0; ks < 4; ks++) {
        uint32_t o = (uint32_t)(w * 16 * 144 + ks * 32);
        LDSM4(qh[ks], AKHI(0) + o + aOff);
        LDSM4(ql[ks], AKLO(0) + o + aOff);
    }
    __syncthreads();

    auto load_kv = [&](int st, int kt) {
        #pragma unroll
        for (int u = 0; u < 4; u++) {
            int idx = tid + u * 128;
            int row = idx >> 3, c16 = idx & 7;
            uint32_t off = (uint32_t)(row * 144 + c16 * 16);
            size_t gk = (size_t)(kt + row) * QKVN + kcol + c16 * 8;
            size_t gv = (size_t)(kt + row) * QKVN + vcol + c16 * 8;
            cp_async16(AKHI(st) + off, qkvhi + gk);
            cp_async16(AKLO(st) + off, qkvlo + gk);
            cp_async16(AVHI(st) + off, qkvhi + gv);
            cp_async16(AVLO(st) + off, qkvlo + gv);
        }
        CP_COMMIT();
    };
    load_kv(0, 0);
    load_kv(1, 64);

    float of[8][4];
    #pragma unroll
    for (int j = 0; j < 8; j++)
        #pragma unroll
        for (int q = 0; q < 4; q++) of[j][q] = 0.f;
    float m0 = -1e30f, m1 = -1e30f, l0 = 0.f, l1 = 0.f;

    for (int it = 0; it < SQ / 64; it++) {
        CP_WAIT(1);
        __syncthreads();
        const int st = it & 1;

        float sf[8][4];
        #pragma unroll
        for (int j = 0; j < 8; j++)
            #pragma unroll
            for (int q = 0; q < 4; q++) sf[j][q] = 0.f;

        #pragma unroll
        for (int ks = 0; ks < 4; ks++) {
            #pragma unroll
            for (int nb = 0; nb < 4; nb++) {
                uint32_t kh[4], kl[4];
                uint32_t o = (uint32_t)(nb * 16 * 144 + ks * 32);
                LDSM4(kh, AKHI(st) + o + bOff);
                LDSM4(kl, AKLO(st) + o + bOff);
                MMA_BF16(sf[2*nb],   qh[ks], kh[0], kh[1]);
                MMA_BF16(sf[2*nb+1], qh[ks], kh[2], kh[3]);
                MMA_BF16(sf[2*nb],   qh[ks], kl[0], kl[1]);
                MMA_BF16(sf[2*nb+1], qh[ks], kl[2], kl[3]);
                MMA_BF16(sf[2*nb],   ql[ks], kh[0], kh[1]);
                MMA_BF16(sf[2*nb+1], ql[ks], kh[2], kh[3]);
            }
        }

        float mx0 = -1e30f, mx1 = -1e30f;
        #pragma unroll
        for (int j = 0; j < 8; j++) {
            #pragma unroll
            for (int q = 0; q < 4; q++) sf[j][q] *= 0.125f;
            mx0 = fmaxf(mx0, fmaxf(sf[j][0], sf[j][1]));
            mx1 = fmaxf(mx1, fmaxf(sf[j][2], sf[j][3]));
        }
        mx0 = fmaxf(mx0, __shfl_xor_sync(0xffffffffu, mx0, 1));
        mx0 = fmaxf(mx0, __shfl_xor_sync(0xffffffffu, mx0, 2));
        mx1 = fmaxf(mx1, __shfl_xor_sync(0xffffffffu, mx1, 1));
        mx1 = fmaxf(mx1, __shfl_xor_sync(0xffffffffu, mx1, 2));
        float mn0 = fmaxf(m0, mx0), mn1 = fmaxf(m1, mx1);
        float sc0 = __expf(m0 - mn0), sc1 = __expf(m1 - mn1);
        m0 = mn0; m1 = mn1;
        float s0 = 0.f, s1 = 0.f;
        #pragma unroll
        for (int j = 0; j < 8; j++) {
            sf[j][0] = __expf(sf[j][0] - mn0); s0 += sf[j][0];
            sf[j][1] = __expf(sf[j][1] - mn0); s0 += sf[j][1];
            sf[j][2] = __expf(sf[j][2] - mn1); s1 += sf[j][2];
            sf[j][3] = __expf(sf[j][3] - mn1); s1 += sf[j][3];
        }
        s0 += __shfl_xor_sync(0xffffffffu, s0, 1);
        s0 += __shfl_xor_sync(0xffffffffu, s0, 2);
        s1 += __shfl_xor_sync(0xffffffffu, s1, 1);
        s1 += __shfl_xor_sync(0xffffffffu, s1, 2);
        l0 = l0 * sc0 + s0;
        l1 = l1 * sc1 + s1;
        #pragma unroll
        for (int j = 0; j < 8; j++) {
            of[j][0] *= sc0; of[j][1] *= sc0;
            of[j][2] *= sc1; of[j][3] *= sc1;
        }

        #pragma unroll
        for (int jp = 0; jp < 4; jp++) {
            uint32_t ph0, ph1, ph2, ph3, pl0, pl1, pl2, pl3;
            split2_bf16(sf[2*jp][0],   sf[2*jp][1],   ph0, pl0);
            split2_bf16(sf[2*jp][2],   sf[2*jp][3],   ph1, pl1);
            split2_bf16(sf[2*jp+1][0], sf[2*jp+1][1], ph2, pl2);
            split2_bf16(sf[2*jp+1][2], sf[2*jp+1][3], ph3, pl3);
            #pragma unroll
            for (int nb = 0; nb < 4; nb++) {
                uint32_t vh[4], vl[4];
                uint32_t o = (uint32_t)(jp * 16 * 144 + nb * 16 * 2);
                LDSM4T(vh, AVHI(st) + o + vOff);
                LDSM4T(vl, AVLO(st) + o + vOff);
                MMA_BF16R(of[2*nb],   ph0, ph1, ph2, ph3, vh[0], vh[1]);
                MMA_BF16R(of[2*nb+1], ph0, ph1, ph2, ph3, vh[2], vh[3]);
                MMA_BF16R(of[2*nb],   ph0, ph1, ph2, ph3, vl[0], vl[1]);
                MMA_BF16R(of[2*nb+1], ph0, ph1, ph2, ph3, vl[2], vl[3]);
                MMA_BF16R(of[2*nb],   pl0, pl1, pl2, pl3, vh[0], vh[1]);
                MMA_BF16R(of[2*nb+1], pl0, pl1, pl2, pl3, vh[2], vh[3]);
            }
        }

        __syncthreads();
        if (it + 2 < SQ / 64) load_kv(st, (it + 2) * 64);
        else                  CP_COMMIT();
    }

    float inv0 = 1.0f / l0, inv1 = 1.0f / l1;
    int r0 = q0 + w * 16 + g;
    #pragma unroll
    for (int j = 0; j < 8; j++) {
        int d = 8 * j + 2 * t4;
        uint32_t h2, l2;
        split2_bf16(of[j][0] * inv0, of[j][1] * inv0, h2, l2);
        *(uint32_t*)(Ohi + (size_t)h * SQ * HDK + (size_t)r0 * HDK + d) = h2;
        *(uint32_t*)(Olo + (size_t)h * SQ * HDK + (size_t)r0 * HDK + d) = l2;
        split2_bf16(of[j][2] * inv1, of[j][3] * inv1, h2, l2);
        *(uint32_t*)(Ohi + (size_t)h * SQ * HDK + (size_t)(r0 + 8) * HDK + d) = h2;
        *(uint32_t*)(Olo + (size_t)h * SQ * HDK + (size_t)(r0 + 8) * HDK + d) = l2;
    }
}

// ---------------- launch ----------------
extern "C" void kernel_launch(void* const* d_in, const int* in_sizes, int n_in,
                              void* d_out, int out_size) {
    const float* x     = (const float*)d_in[0];
    const float* wq    = (const float*)d_in[1];
    const float* bq    = (const float*)d_in[2];
    const float* wk    = (const float*)d_in[3];
    const float* bk    = (const float*)d_in[4];
    const float* wv    = (const float*)d_in[5];
    const float* bv    = (const float*)d_in[6];
    const float* wo    = (const float*)d_in[7];
    const float* bo    = (const float*)d_in[8];
    const float* w1    = (const float*)d_in[9];
    const float* b1    = (const float*)d_in[10];
    const float* w2    = (const float*)d_in[11];
    const float* b2    = (const float*)d_in[12];
    const float* ln1_g = (const float*)d_in[13];
    const float* ln1_b = (const float*)d_in[14];
    const float* ln2_g = (const float*)d_in[15];
    const float* ln2_b = (const float*)d_in[16];
    float* out = (float*)d_out;

    unsigned short *hhi, *hlo, *qkvh, *qkvl, *aohi, *aolo, *fhi, *flo;
    unsigned short *wqkvh, *wqkvl, *woh, *wol, *w1h, *w1l, *w2h, *w2l;
    float *x1, *bqkv;
    cudaGetSymbolAddress((void**)&hhi,  g_h_hi);  cudaGetSymbolAddress((void**)&hlo,  g_h_lo);
    cudaGetSymbolAddress((void**)&qkvh, g_qkv_hi); cudaGetSymbolAddress((void**)&qkvl, g_qkv_lo);
    cudaGetSymbolAddress((void**)&aohi, g_ao_hi); cudaGetSymbolAddress((void**)&aolo, g_ao_lo);
    cudaGetSymbolAddress((void**)&x1,   g_x1);
    cudaGetSymbolAddress((void**)&fhi,  g_f_hi);  cudaGetSymbolAddress((void**)&flo,  g_f_lo);
    cudaGetSymbolAddress((void**)&wqkvh, g_wqkv_hi); cudaGetSymbolAddress((void**)&wqkvl, g_wqkv_lo);
    cudaGetSymbolAddress((void**)&woh,  g_wo_hi); cudaGetSymbolAddress((void**)&wol,  g_wo_lo);
    cudaGetSymbolAddress((void**)&w1h,  g_w1_hi); cudaGetSymbolAddress((void**)&w1l,  g_w1_lo);
    cudaGetSymbolAddress((void**)&w2h,  g_w2_hi); cudaGetSymbolAddress((void**)&w2l,  g_w2_lo);
    cudaGetSymbolAddress((void**)&bqkv, g_bqkv);

    cudaFuncSetAttribute(gemm_mma_kernel,
                         cudaFuncAttributeMaxDynamicSharedMemorySize, GEMM_SMEM);
    cudaFuncSetAttribute(attn_mma_kernel,
                         cudaFuncAttributeMaxDynamicSharedMemorySize, ATT_SMEM);

    dim3 tb(32, 8);

    // Launch order arranged so the QKV GEMM is launch index 5 (ncu -s 5 -c 1).
    // idx 0: LN1 (depends only on x)
    ln_split_kernel<<<SQ, 256>>>(x, ln1_g, ln1_b, hhi, hlo);
    // idx 1: merged QKV weight transpose
    transpose_qkv_kernel<<<dim3(DIM/32, DIM/32, 3), tb>>>(wq, wk, wv, wqkvh, wqkvl);
    // idx 2: bias concat
    concat_bias_kernel<<<QKVN/256, 256>>>(bq, bk, bv, bqkv);
    // idx 3-4: wo / w1 transposes (independent)
    transpose_split_kernel<<<dim3(DIM/32,  DIM/32),  tb>>>(wo, DIM,  DIM,  woh, wol);
    transpose_split_kernel<<<dim3(MLPD/32, DIM/32),  tb>>>(w1, DIM,  MLPD, w1h, w1l);
    // idx 5: QKV fused GEMM  <-- ncu capture target
    gemm_mma_kernel<<<dim3(QKVN/128, SQ/128), 256, GEMM_SMEM>>>(
        hhi, hlo, wqkvh, wqkvl, bqkv, nullptr, nullptr, qkvh, qkvl, QKVN, DIM, 0);
    // idx 6: w2 transpose (independent of everything above)
    transpose_split_kernel<<<dim3(DIM/32,  MLPD/32), tb>>>(w2, MLPD, DIM,  w2h, w2l);
    // attention -> ao hi/lo
    attn_mma_kernel<<<dim3(SQ/64, NH), 128, ATT_SMEM>>>(qkvh, qkvl, aohi, aolo);
    // O-proj + residual(x) -> x1 fp32
    gemm_mma_kernel<<<dim3(DIM/128, SQ/128), 256, GEMM_SMEM>>>(
        aohi, aolo, woh, wol, bo, x, x1, nullptr, nullptr, DIM, DIM, 0);
    // LN2 -> split
    ln_split_kernel<<<SQ, 256>>>(x1, ln2_g, ln2_b, hhi, hlo);
    // FFN1 + GELU -> f hi/lo
    gemm_mma_kernel<<<dim3(MLPD/128, SQ/128), 256, GEMM_SMEM>>>(
        hhi, hlo, w1h, w1l, b1, nullptr, nullptr, fhi, flo, MLPD, DIM, 1);
    // FFN2 + residual(x1) -> out fp32
    gemm_mma_kernel<<<dim3(DIM/128, SQ/128), 256, GEMM_SMEM>>>(
        fhi, flo, w2h, w2l, b2, x1, out, nullptr, nullptr, DIM, MLPD, 0);
}

// round 6
// speedup vs baseline: 4.2542x; 1.4032x over previous
#include <cuda_runtime.h>
#include <cuda_fp16.h>
#include <math.h>
#include <stdint.h>

#define SQ   2048
#define DIM  1024
#define NH   16
#define HDK  64
#define MLPD 4096
#define QKVN 3072

// ---------------- scratch (no allocations allowed) ----------------
__device__ unsigned short g_h   [SQ*DIM];                 // fp16 activations (LN out)
__device__ unsigned short g_qkv_hi[SQ*QKVN], g_qkv_lo[SQ*QKVN];
__device__ unsigned short g_ao  [SQ*DIM];                 // attention out fp16
__device__ float          g_x1  [SQ*DIM];
__device__ unsigned short g_f   [SQ*MLPD];                // gelu out fp16
__device__ unsigned short g_wqkv_hi[QKVN*DIM], g_wqkv_lo[QKVN*DIM];
__device__ unsigned short g_wo_hi [DIM*DIM],   g_wo_lo [DIM*DIM];
__device__ unsigned short g_w1_hi [MLPD*DIM],  g_w1_lo [MLPD*DIM];
__device__ unsigned short g_w2_hi [DIM*MLPD],  g_w2_lo [DIM*MLPD];
__device__ float          g_bqkv[QKVN];

// ---------------- helpers ----------------
__device__ __forceinline__ uint32_t smem_u32(const void* p) {
    uint32_t a;
    asm("{ .reg .u64 t; cvta.to.shared.u64 t, %1; cvt.u32.u64 %0, t; }" : "=r"(a) : "l"(p));
    return a;
}

__device__ __forceinline__ void cp_async16(uint32_t sdst, const void* gsrc) {
    asm volatile("cp.async.cg.shared.global [%0], [%1], 16;" :: "r"(sdst), "l"(gsrc) : "memory");
}
#define CP_COMMIT() asm volatile("cp.async.commit_group;" ::: "memory")
#define CP_WAIT(n)  asm volatile("cp.async.wait_group %0;" :: "n"(n) : "memory")

#define LDSM4(r, addr) \
    asm volatile("ldmatrix.sync.aligned.m8n8.x4.shared.b16 {%0,%1,%2,%3}, [%4];" \
        : "=r"((r)[0]), "=r"((r)[1]), "=r"((r)[2]), "=r"((r)[3]) : "r"(addr))

#define LDSM4T(r, addr) \
    asm volatile("ldmatrix.sync.aligned.m8n8.x4.trans.shared.b16 {%0,%1,%2,%3}, [%4];" \
        : "=r"((r)[0]), "=r"((r)[1]), "=r"((r)[2]), "=r"((r)[3]) : "r"(addr))

#define MMA_F16(c, a, b0, b1) \
    asm volatile("mma.sync.aligned.m16n8k16.row.col.f32.f16.f16.f32 " \
        "{%0,%1,%2,%3}, {%4,%5,%6,%7}, {%8,%9}, {%0,%1,%2,%3};" \
        : "+f"((c)[0]), "+f"((c)[1]), "+f"((c)[2]), "+f"((c)[3]) \
        : "r"((a)[0]), "r"((a)[1]), "r"((a)[2]), "r"((a)[3]), "r"(b0), "r"(b1))

#define MMA_F16R(c, a0, a1, a2, a3, b0, b1) \
    asm volatile("mma.sync.aligned.m16n8k16.row.col.f32.f16.f16.f32 " \
        "{%0,%1,%2,%3}, {%4,%5,%6,%7}, {%8,%9}, {%0,%1,%2,%3};" \
        : "+f"((c)[0]), "+f"((c)[1]), "+f"((c)[2]), "+f"((c)[3]) \
        : "r"(a0), "r"(a1), "r"(a2), "r"(a3), "r"(b0), "r"(b1))

__device__ __forceinline__ unsigned short f2h(float v) {
    return __half_as_ushort(__float2half_rn(v));
}
__device__ __forceinline__ uint32_t pack2_h(float a, float b) {
    __half2 h = __floats2half2_rn(a, b);
    return *(uint32_t*)&h;
}
// fp16 hi/lo split of a pair, packed
__device__ __forceinline__ void split2_h(float a, float b, uint32_t& hi2, uint32_t& lo2) {
    __half ha = __float2half_rn(a), hb = __float2half_rn(b);
    float ra = a - __half2float(ha), rb = b - __half2float(hb);
    __half la = __float2half_rn(ra), lb = __float2half_rn(rb);
    hi2 = (uint32_t)__half_as_ushort(ha) | ((uint32_t)__half_as_ushort(hb) << 16);
    lo2 = (uint32_t)__half_as_ushort(la) | ((uint32_t)__half_as_ushort(lb) << 16);
}
__device__ __forceinline__ void split_h(float v, unsigned short& hi, unsigned short& lo) {
    __half h = __float2half_rn(v);
    float r = v - __half2float(h);
    hi = __half_as_ushort(h);
    lo = __half_as_ushort(__float2half_rn(r));
}

// ---------------- layernorm -> fp16 ----------------
__device__ __forceinline__ float block_sum_256(float v, float* sh) {
    int lane = threadIdx.x & 31, w = threadIdx.x >> 5;
    #pragma unroll
    for (int o = 16; o; o >>= 1) v += __shfl_xor_sync(0xffffffffu, v, o);
    __syncthreads();
    if (lane == 0) sh[w] = v;
    __syncthreads();
    float r = 0.f;
    #pragma unroll
    for (int i = 0; i < 8; i++) r += sh[i];
    return r;
}

__global__ void ln_h_kernel(const float* __restrict__ x, const float* __restrict__ g,
                            const float* __restrict__ b, unsigned short* __restrict__ oh) {
    __shared__ float sh[8];
    int row = blockIdx.x;
    const float* xr = x + (size_t)row * DIM;
    int t = threadIdx.x;
    float v0[4];
    float s = 0.f;
    #pragma unroll
    for (int u = 0; u < 4; u++) { v0[u] = xr[t + u * 256]; s += v0[u]; }
    s = block_sum_256(s, sh);
    float mean = s * (1.0f / DIM);
    float vs = 0.f;
    #pragma unroll
    for (int u = 0; u < 4; u++) { float d = v0[u] - mean; vs += d * d; }
    vs = block_sum_256(vs, sh);
    float rstd = rsqrtf(vs * (1.0f / DIM) + 1e-5f);
    #pragma unroll
    for (int u = 0; u < 4; u++) {
        int c = t + u * 256;
        oh[(size_t)row * DIM + c] = f2h((v0[u] - mean) * rstd * g[c] + b[c]);
    }
}

// ---------------- weight transpose + fp16 split ----------------
__global__ void transpose_split_kernel(const float* __restrict__ in, int R, int C,
                                       unsigned short* __restrict__ hi, unsigned short* __restrict__ lo) {
    __shared__ float t[32][33];
    int c0 = blockIdx.x * 32, r0 = blockIdx.y * 32;
    #pragma unroll
    for (int u = 0; u < 4; u++) {
        int r = r0 + threadIdx.y + u * 8;
        t[threadIdx.y + u * 8][threadIdx.x] = in[(size_t)r * C + c0 + threadIdx.x];
    }
    __syncthreads();
    #pragma unroll
    for (int u = 0; u < 4; u++) {
        int c = c0 + threadIdx.y + u * 8;
        float v = t[threadIdx.x][threadIdx.y + u * 8];
        unsigned short h, l;
        split_h(v, h, l);
        hi[(size_t)c * R + r0 + threadIdx.x] = h;
        lo[(size_t)c * R + r0 + threadIdx.x] = l;
    }
}

__global__ void transpose_qkv_kernel(const float* __restrict__ wq, const float* __restrict__ wk,
                                     const float* __restrict__ wv,
                                     unsigned short* __restrict__ hi, unsigned short* __restrict__ lo) {
    __shared__ float t[32][33];
    const float* in = (blockIdx.z == 0) ? wq : (blockIdx.z == 1) ? wk : wv;
    unsigned short* hiz = hi + (size_t)blockIdx.z * DIM * DIM;
    unsigned short* loz = lo + (size_t)blockIdx.z * DIM * DIM;
    int c0 = blockIdx.x * 32, r0 = blockIdx.y * 32;
    #pragma unroll
    for (int u = 0; u < 4; u++) {
        int r = r0 + threadIdx.y + u * 8;
        t[threadIdx.y + u * 8][threadIdx.x] = in[(size_t)r * DIM + c0 + threadIdx.x];
    }
    __syncthreads();
    #pragma unroll
    for (int u = 0; u < 4; u++) {
        int c = c0 + threadIdx.y + u * 8;
        float v = t[threadIdx.x][threadIdx.y + u * 8];
        unsigned short h, l;
        split_h(v, h, l);
        hiz[(size_t)c * DIM + r0 + threadIdx.x] = h;
        loz[(size_t)c * DIM + r0 + threadIdx.x] = l;
    }
}

__global__ void concat_bias_kernel(const float* __restrict__ bq, const float* __restrict__ bk,
                                   const float* __restrict__ bv, float* __restrict__ out) {
    int i = blockIdx.x * 256 + threadIdx.x;
    if (i < DIM) out[i] = bq[i];
    else if (i < 2 * DIM) out[i] = bk[i - DIM];
    else if (i < 3 * DIM) out[i] = bv[i - 2 * DIM];
}

// ---------------- fp16x2 GEMM: C = A_f16 @ (Bhi+Blo)^T ----------------
// 128x128 CTA tile, BK=32, 3 tiles/stage (A, Bhi, Blo), 3 stages, 2 CTAs/SM.
#define TILEB 10240u
#define STAGES 3
#define GEMM_SMEM (STAGES * 3 * 10240)

__global__ __launch_bounds__(256, 2)
void gemm_mma_kernel(const unsigned short* __restrict__ A,
                     const unsigned short* __restrict__ Bhi, const unsigned short* __restrict__ Blo,
                     const float* __restrict__ bias, const float* __restrict__ res,
                     float* __restrict__ outF,
                     unsigned short* __restrict__ outHi, unsigned short* __restrict__ outLo,
                     int N, int K, int gelu) {
    extern __shared__ char smem[];
    const uint32_t sb = smem_u32(smem);
    const int tid  = threadIdx.x;
    const int wid  = tid >> 5;
    const int lane = tid & 31;
    const int wm = wid >> 2;
    const int wn = wid & 3;
    const int bm = blockIdx.y * 128;
    const int bn = blockIdx.x * 128;
    const int g  = lane >> 2;
    const int t4 = lane & 3;

    const uint32_t aOff = (uint32_t)((((lane >> 3) & 1) * 8 + (lane & 7)) * 80 + (lane >> 4) * 16);
    const uint32_t bOff = (uint32_t)(((lane >> 4) * 8 + (lane & 7)) * 80 + ((lane >> 3) & 1) * 16);

    float acc[4][4][4];
    #pragma unroll
    for (int i = 0; i < 4; i++)
        #pragma unroll
        for (int j = 0; j < 4; j++)
            #pragma unroll
            for (int q = 0; q < 4; q++) acc[i][j][q] = 0.f;

    const int NCH = K >> 5;
    const unsigned short* gsrc[3] = {A, Bhi, Blo};
    const int rbase[3] = {bm, bn, bn};

    auto load_chunk = [&](int stage, int k0) {
        #pragma unroll
        for (int t = 0; t < 3; t++) {
            uint32_t dst = sb + (uint32_t)(stage * 3 + t) * TILEB;
            const unsigned short* gp = gsrc[t];
            #pragma unroll
            for (int u = 0; u < 2; u++) {
                int idx = tid + 256 * u;
                int r = idx >> 2;
                int cc = idx & 3;
                cp_async16(dst + (uint32_t)(r * 80 + cc * 16),
                           gp + (size_t)(rbase[t] + r) * K + k0 + cc * 8);
            }
        }
        CP_COMMIT();
    };

    #pragma unroll
    for (int s = 0; s < STAGES; s++) load_chunk(s, s * 32);

    int st = 0;
    for (int i = 0; i < NCH; i++) {
        CP_WAIT(STAGES - 1);
        __syncthreads();

        const uint32_t base = sb + (uint32_t)(st * 3) * TILEB;
        const uint32_t aB   = base;
        const uint32_t bHiB = base + TILEB;
        const uint32_t bLoB = base + 2*TILEB;

        #pragma unroll
        for (int ks = 0; ks < 2; ks++) {
            uint32_t bh[2][4], bl[2][4];
            #pragma unroll
            for (int np = 0; np < 2; np++) {
                uint32_t o = (uint32_t)((wn * 32 + np * 16) * 80 + ks * 32) + bOff;
                LDSM4(bh[np], bHiB + o);
                LDSM4(bl[np], bLoB + o);
            }
            #pragma unroll
            for (int mt = 0; mt < 4; mt++) {
                uint32_t af[4];
                uint32_t o = (uint32_t)((wm * 64 + mt * 16) * 80 + ks * 32) + aOff;
                LDSM4(af, aB + o);
                #pragma unroll
                for (int nt = 0; nt < 4; nt++) {
                    int np = nt >> 1, sub = (nt & 1) * 2;
                    MMA_F16(acc[mt][nt], af, bh[np][sub], bh[np][sub + 1]);
                    MMA_F16(acc[mt][nt], af, bl[np][sub], bl[np][sub + 1]);
                }
            }
        }
        __syncthreads();

        if (i + STAGES < NCH) load_chunk(st, (i + STAGES) * 32);
        else                  CP_COMMIT();
        st = (st + 1 == STAGES) ? 0 : st + 1;
    }

    // --- epilogue ---
    #pragma unroll
    for (int mt = 0; mt < 4; mt++) {
        int r0 = bm + wm * 64 + mt * 16 + g;
        #pragma unroll
        for (int nt = 0; nt < 4; nt++) {
            int c = bn + wn * 32 + nt * 8 + t4 * 2;
            float v[4];
            v[0] = acc[mt][nt][0] + bias[c];
            v[1] = acc[mt][nt][1] + bias[c + 1];
            v[2] = acc[mt][nt][2] + bias[c];
            v[3] = acc[mt][nt][3] + bias[c + 1];
            if (gelu) {
                #pragma unroll
                for (int q = 0; q < 4; q++)
                    v[q] = 0.5f * v[q] * (1.0f + erff(v[q] * 0.70710678118654752f));
            }
            if (res) {
                v[0] += res[(size_t)r0 * N + c];
                v[1] += res[(size_t)r0 * N + c + 1];
                v[2] += res[(size_t)(r0 + 8) * N + c];
                v[3] += res[(size_t)(r0 + 8) * N + c + 1];
            }
            if (outF) {
                *(float2*)(outF + (size_t)r0 * N + c)       = make_float2(v[0], v[1]);
                *(float2*)(outF + (size_t)(r0 + 8) * N + c) = make_float2(v[2], v[3]);
            } else if (outLo) {
                uint32_t h2, l2;
                split2_h(v[0], v[1], h2, l2);
                *(uint32_t*)(outHi + (size_t)r0 * N + c) = h2;
                *(uint32_t*)(outLo + (size_t)r0 * N + c) = l2;
                split2_h(v[2], v[3], h2, l2);
                *(uint32_t*)(outHi + (size_t)(r0 + 8) * N + c) = h2;
                *(uint32_t*)(outLo + (size_t)(r0 + 8) * N + c) = l2;
            } else {
                *(uint32_t*)(outHi + (size_t)r0 * N + c)       = pack2_h(v[0], v[1]);
                *(uint32_t*)(outHi + (size_t)(r0 + 8) * N + c) = pack2_h(v[2], v[3]);
            }
        }
    }
}

// ---------------- flash attention, fp16x2 ----------------
// Q single fp16 (hi buffer), K/V fp16 hi+lo, P single fp16.
#define ATILE 9216u
#define ATT_SMEM (2 * 4 * 9216)

__global__ __launch_bounds__(128)
void attn_mma_kernel(const unsigned short* __restrict__ qkvhi,
                     const unsigned short* __restrict__ qkvlo,
                     unsigned short* __restrict__ O) {
    extern __shared__ char smem[];
    const uint32_t sb = smem_u32(smem);
    const int h  = blockIdx.y;
    const int q0 = blockIdx.x * 64;
    const int tid = threadIdx.x;
    const int w = tid >> 5, lane = tid & 31;
    const int g = lane >> 2, t4 = lane & 3;
    const int qcol = h * HDK, kcol = DIM + h * HDK, vcol = 2 * DIM + h * HDK;

    const uint32_t aOff = (uint32_t)((((lane >> 3) & 1) * 8 + (lane & 7)) * 144 + (lane >> 4) * 16);
    const uint32_t bOff = (uint32_t)(((lane >> 4) * 8 + (lane & 7)) * 144 + ((lane >> 3) & 1) * 16);
    const uint32_t vOff = (uint32_t)((lane & 15) * 144 + (lane >> 4) * 16);

    #define AKHI(s) (sb + (uint32_t)(s) * 4u * ATILE)
    #define AKLO(s) (AKHI(s) + ATILE)
    #define AVHI(s) (AKHI(s) + 2u * ATILE)
    #define AVLO(s) (AKHI(s) + 3u * ATILE)

    // stage Q (hi only) through smem into registers
    #pragma unroll
    for (int u = 0; u < 4; u++) {
        int idx = tid + u * 128;
        int row = idx >> 3, c16 = idx & 7;
        uint32_t off = (uint32_t)(row * 144 + c16 * 16);
        cp_async16(AKHI(0) + off, qkvhi + (size_t)(q0 + row) * QKVN + qcol + c16 * 8);
    }
    CP_COMMIT(); CP_WAIT(0); __syncthreads();

    uint32_t qh[4][4];
    #pragma unroll
    for (int ks = 0; ks < 4; ks++) {
        uint32_t o = (uint32_t)(w * 16 * 144 + ks * 32);
        LDSM4(qh[ks], AKHI(0) + o + aOff);
    }
    __syncthreads();

    auto load_kv = [&](int st, int kt) {
        #pragma unroll
        for (int u = 0; u < 4; u++) {
            int idx = tid + u * 128;
            int row = idx >> 3, c16 = idx & 7;
            uint32_t off = (uint32_t)(row * 144 + c16 * 16);
            size_t gk = (size_t)(kt + row) * QKVN + kcol + c16 * 8;
            size_t gv = (size_t)(kt + row) * QKVN + vcol + c16 * 8;
            cp_async16(AKHI(st) + off, qkvhi + gk);
            cp_async16(AKLO(st) + off, qkvlo + gk);
            cp_async16(AVHI(st) + off, qkvhi + gv);
            cp_async16(AVLO(st) + off, qkvlo + gv);
        }
        CP_COMMIT();
    };
    load_kv(0, 0);
    load_kv(1, 64);

    float of[8][4];
    #pragma unroll
    for (int j = 0; j < 8; j++)
        #pragma unroll
        for (int q = 0; q < 4; q++) of[j][q] = 0.f;
    float m0 = -1e30f, m1 = -1e30f, l0 = 0.f, l1 = 0.f;

    for (int it = 0; it < SQ / 64; it++) {
        CP_WAIT(1);
        __syncthreads();
        const int st = it & 1;

        float sf[8][4];
        #pragma unroll
        for (int j = 0; j < 8; j++)
            #pragma unroll
            for (int q = 0; q < 4; q++) sf[j][q] = 0.f;

        #pragma unroll
        for (int ks = 0; ks < 4; ks++) {
            #pragma unroll
            for (int nb = 0; nb < 4; nb++) {
                uint32_t kh[4], kl[4];
                uint32_t o = (uint32_t)(nb * 16 * 144 + ks * 32);
                LDSM4(kh, AKHI(st) + o + bOff);
                LDSM4(kl, AKLO(st) + o + bOff);
                MMA_F16(sf[2*nb],   qh[ks], kh[0], kh[1]);
                MMA_F16(sf[2*nb+1], qh[ks], kh[2], kh[3]);
                MMA_F16(sf[2*nb],   qh[ks], kl[0], kl[1]);
                MMA_F16(sf[2*nb+1], qh[ks], kl[2], kl[3]);
            }
        }

        float mx0 = -1e30f, mx1 = -1e30f;
        #pragma unroll
        for (int j = 0; j < 8; j++) {
            #pragma unroll
            for (int q = 0; q < 4; q++) sf[j][q] *= 0.125f;
            mx0 = fmaxf(mx0, fmaxf(sf[j][0], sf[j][1]));
            mx1 = fmaxf(mx1, fmaxf(sf[j][2], sf[j][3]));
        }
        mx0 = fmaxf(mx0, __shfl_xor_sync(0xffffffffu, mx0, 1));
        mx0 = fmaxf(mx0, __shfl_xor_sync(0xffffffffu, mx0, 2));
        mx1 = fmaxf(mx1, __shfl_xor_sync(0xffffffffu, mx1, 1));
        mx1 = fmaxf(mx1, __shfl_xor_sync(0xffffffffu, mx1, 2));
        float mn0 = fmaxf(m0, mx0), mn1 = fmaxf(m1, mx1);
        float sc0 = __expf(m0 - mn0), sc1 = __expf(m1 - mn1);
        m0 = mn0; m1 = mn1;
        float s0 = 0.f, s1 = 0.f;
        #pragma unroll
        for (int j = 0; j < 8; j++) {
            sf[j][0] = __expf(sf[j][0] - mn0); s0 += sf[j][0];
            sf[j][1] = __expf(sf[j][1] - mn0); s0 += sf[j][1];
            sf[j][2] = __expf(sf[j][2] - mn1); s1 += sf[j][2];
            sf[j][3] = __expf(sf[j][3] - mn1); s1 += sf[j][3];
        }
        s0 += __shfl_xor_sync(0xffffffffu, s0, 1);
        s0 += __shfl_xor_sync(0xffffffffu, s0, 2);
        s1 += __shfl_xor_sync(0xffffffffu, s1, 1);
        s1 += __shfl_xor_sync(0xffffffffu, s1, 2);
        l0 = l0 * sc0 + s0;
        l1 = l1 * sc1 + s1;
        #pragma unroll
        for (int j = 0; j < 8; j++) {
            of[j][0] *= sc0; of[j][1] *= sc0;
            of[j][2] *= sc1; of[j][3] *= sc1;
        }

        #pragma unroll
        for (int jp = 0; jp < 4; jp++) {
            uint32_t p0 = pack2_h(sf[2*jp][0],   sf[2*jp][1]);
            uint32_t p1 = pack2_h(sf[2*jp][2],   sf[2*jp][3]);
            uint32_t p2 = pack2_h(sf[2*jp+1][0], sf[2*jp+1][1]);
            uint32_t p3 = pack2_h(sf[2*jp+1][2], sf[2*jp+1][3]);
            #pragma unroll
            for (int nb = 0; nb < 4; nb++) {
                uint32_t vh[4], vl[4];
                uint32_t o = (uint32_t)(jp * 16 * 144 + nb * 16 * 2);
                LDSM4T(vh, AVHI(st) + o + vOff);
                LDSM4T(vl, AVLO(st) + o + vOff);
                MMA_F16R(of[2*nb],   p0, p1, p2, p3, vh[0], vh[1]);
                MMA_F16R(of[2*nb+1], p0, p1, p2, p3, vh[2], vh[3]);
                MMA_F16R(of[2*nb],   p0, p1, p2, p3, vl[0], vl[1]);
                MMA_F16R(of[2*nb+1], p0, p1, p2, p3, vl[2], vl[3]);
            }
        }

        __syncthreads();
        if (it + 2 < SQ / 64) load_kv(st, (it + 2) * 64);
        else                  CP_COMMIT();
    }

    float inv0 = 1.0f / l0, inv1 = 1.0f / l1;
    int r0 = q0 + w * 16 + g;
    #pragma unroll
    for (int j = 0; j < 8; j++) {
        int d = 8 * j + 2 * t4;
        *(uint32_t*)(O + (size_t)h * SQ * HDK + (size_t)r0 * HDK + d) =
            pack2_h(of[j][0] * inv0, of[j][1] * inv0);
        *(uint32_t*)(O + (size_t)h * SQ * HDK + (size_t)(r0 + 8) * HDK + d) =
            pack2_h(of[j][2] * inv1, of[j][3] * inv1);
    }
}

// ---------------- launch ----------------
extern "C" void kernel_launch(void* const* d_in, const int* in_sizes, int n_in,
                              void* d_out, int out_size) {
    const float* x     = (const float*)d_in[0];
    const float* wq    = (const float*)d_in[1];
    const float* bq    = (const float*)d_in[2];
    const float* wk    = (const float*)d_in[3];
    const float* bk    = (const float*)d_in[4];
    const float* wv    = (const float*)d_in[5];
    const float* bv    = (const float*)d_in[6];
    const float* wo    = (const float*)d_in[7];
    const float* bo    = (const float*)d_in[8];
    const float* w1    = (const float*)d_in[9];
    const float* b1    = (const float*)d_in[10];
    const float* w2    = (const float*)d_in[11];
    const float* b2    = (const float*)d_in[12];
    const float* ln1_g = (const float*)d_in[13];
    const float* ln1_b = (const float*)d_in[14];
    const float* ln2_g = (const float*)d_in[15];
    const float* ln2_b = (const float*)d_in[16];
    float* out = (float*)d_out;

    unsigned short *hh, *qkvh, *qkvl, *ao, *f;
    unsigned short *wqkvh, *wqkvl, *woh, *wol, *w1h, *w1l, *w2h, *w2l;
    float *x1, *bqkv;
    cudaGetSymbolAddress((void**)&hh,   g_h);
    cudaGetSymbolAddress((void**)&qkvh, g_qkv_hi); cudaGetSymbolAddress((void**)&qkvl, g_qkv_lo);
    cudaGetSymbolAddress((void**)&ao,   g_ao);
    cudaGetSymbolAddress((void**)&x1,   g_x1);
    cudaGetSymbolAddress((void**)&f,    g_f);
    cudaGetSymbolAddress((void**)&wqkvh, g_wqkv_hi); cudaGetSymbolAddress((void**)&wqkvl, g_wqkv_lo);
    cudaGetSymbolAddress((void**)&woh,  g_wo_hi); cudaGetSymbolAddress((void**)&wol,  g_wo_lo);
    cudaGetSymbolAddress((void**)&w1h,  g_w1_hi); cudaGetSymbolAddress((void**)&w1l,  g_w1_lo);
    cudaGetSymbolAddress((void**)&w2h,  g_w2_hi); cudaGetSymbolAddress((void**)&w2l,  g_w2_lo);
    cudaGetSymbolAddress((void**)&bqkv, g_bqkv);

    cudaFuncSetAttribute(gemm_mma_kernel,
                         cudaFuncAttributeMaxDynamicSharedMemorySize, GEMM_SMEM);
    cudaFuncSetAttribute(attn_mma_kernel,
                         cudaFuncAttributeMaxDynamicSharedMemorySize, ATT_SMEM);

    dim3 tb(32, 8);

    // prep
    ln_h_kernel<<<SQ, 256>>>(x, ln1_g, ln1_b, hh);
    transpose_qkv_kernel<<<dim3(DIM/32, DIM/32, 3), tb>>>(wq, wk, wv, wqkvh, wqkvl);
    concat_bias_kernel<<<QKVN/256, 256>>>(bq, bk, bv, bqkv);
    transpose_split_kernel<<<dim3(DIM/32,  DIM/32),  tb>>>(wo, DIM,  DIM,  woh, wol);
    transpose_split_kernel<<<dim3(MLPD/32, DIM/32),  tb>>>(w1, DIM,  MLPD, w1h, w1l);
    // QKV fused GEMM -> fp16 hi/lo (attention needs K/V hi+lo)
    gemm_mma_kernel<<<dim3(QKVN/128, SQ/128), 256, GEMM_SMEM>>>(
        hh, wqkvh, wqkvl, bqkv, nullptr, nullptr, qkvh, qkvl, QKVN, DIM, 0);
    transpose_split_kernel<<<dim3(DIM/32,  MLPD/32), tb>>>(w2, MLPD, DIM,  w2h, w2l);
    // attention -> ao fp16
    attn_mma_kernel<<<dim3(SQ/64, NH), 128, ATT_SMEM>>>(qkvh, qkvl, ao);
    // O-proj + residual(x) -> x1 fp32
    gemm_mma_kernel<<<dim3(DIM/128, SQ/128), 256, GEMM_SMEM>>>(
        ao, woh, wol, bo, x, x1, nullptr, nullptr, DIM, DIM, 0);
    // LN2 -> fp16
    ln_h_kernel<<<SQ, 256>>>(x1, ln2_g, ln2_b, hh);
    // FFN1 + GELU -> f fp16 (single)
    gemm_mma_kernel<<<dim3(MLPD/128, SQ/128), 256, GEMM_SMEM>>>(
        hh, w1h, w1l, b1, nullptr, nullptr, f, nullptr, MLPD, DIM, 1);
    // FFN2 + residual(x1) -> out fp32
    gemm_mma_kernel<<<dim3(DIM/128, SQ/128), 256, GEMM_SMEM>>>(
        f, w2h, w2l, b2, x1, out, nullptr, nullptr, DIM, MLPD, 0);
}

// round 7
// speedup vs baseline: 7.1015x; 1.6693x over previous
#include <cuda_runtime.h>
#include <cuda_fp16.h>
#include <math.h>
#include <stdint.h>

#define SQ   2048
#define DIM  1024
#define NH   16
#define HDK  64
#define MLPD 4096
#define QKVN 3072

// ---------------- scratch (no allocations allowed) ----------------
__device__ unsigned short g_h   [SQ*DIM];     // fp16 LN out
__device__ unsigned short g_qkv [SQ*QKVN];    // fp16 q,k,v
__device__ unsigned short g_ao  [SQ*DIM];     // fp16 attention out [H,S,DK]
__device__ float          g_x1  [SQ*DIM];
__device__ unsigned short g_f   [SQ*MLPD];    // fp16 gelu out
__device__ unsigned short g_wqkv[QKVN*DIM];   // fp16 weights, [N,K]
__device__ unsigned short g_wo  [DIM*DIM];
__device__ unsigned short g_w1  [MLPD*DIM];
__device__ unsigned short g_w2  [DIM*MLPD];
__device__ float          g_bqkv[QKVN];

// ---------------- helpers ----------------
__device__ __forceinline__ uint32_t smem_u32(const void* p) {
    uint32_t a;
    asm("{ .reg .u64 t; cvta.to.shared.u64 t, %1; cvt.u32.u64 %0, t; }" : "=r"(a) : "l"(p));
    return a;
}

__device__ __forceinline__ void cp_async16(uint32_t sdst, const void* gsrc) {
    asm volatile("cp.async.cg.shared.global [%0], [%1], 16;" :: "r"(sdst), "l"(gsrc) : "memory");
}
#define CP_COMMIT() asm volatile("cp.async.commit_group;" ::: "memory")
#define CP_WAIT(n)  asm volatile("cp.async.wait_group %0;" :: "n"(n) : "memory")

#define LDSM4(r, addr) \
    asm volatile("ldmatrix.sync.aligned.m8n8.x4.shared.b16 {%0,%1,%2,%3}, [%4];" \
        : "=r"((r)[0]), "=r"((r)[1]), "=r"((r)[2]), "=r"((r)[3]) : "r"(addr))

#define LDSM4T(r, addr) \
    asm volatile("ldmatrix.sync.aligned.m8n8.x4.trans.shared.b16 {%0,%1,%2,%3}, [%4];" \
        : "=r"((r)[0]), "=r"((r)[1]), "=r"((r)[2]), "=r"((r)[3]) : "r"(addr))

#define MMA_F16(c, a, b0, b1) \
    asm volatile("mma.sync.aligned.m16n8k16.row.col.f32.f16.f16.f32 " \
        "{%0,%1,%2,%3}, {%4,%5,%6,%7}, {%8,%9}, {%0,%1,%2,%3};" \
        : "+f"((c)[0]), "+f"((c)[1]), "+f"((c)[2]), "+f"((c)[3]) \
        : "r"((a)[0]), "r"((a)[1]), "r"((a)[2]), "r"((a)[3]), "r"(b0), "r"(b1))

#define MMA_F16R(c, a0, a1, a2, a3, b0, b1) \
    asm volatile("mma.sync.aligned.m16n8k16.row.col.f32.f16.f16.f32 " \
        "{%0,%1,%2,%3}, {%4,%5,%6,%7}, {%8,%9}, {%0,%1,%2,%3};" \
        : "+f"((c)[0]), "+f"((c)[1]), "+f"((c)[2]), "+f"((c)[3]) \
        : "r"(a0), "r"(a1), "r"(a2), "r"(a3), "r"(b0), "r"(b1))

__device__ __forceinline__ unsigned short f2h(float v) {
    return __half_as_ushort(__float2half_rn(v));
}
__device__ __forceinline__ uint32_t pack2_h(float a, float b) {
    __half2 h = __floats2half2_rn(a, b);
    return *(uint32_t*)&h;
}

// ---------------- layernorm -> fp16 ----------------
__device__ __forceinline__ float block_sum_256(float v, float* sh) {
    int lane = threadIdx.x & 31, w = threadIdx.x >> 5;
    #pragma unroll
    for (int o = 16; o; o >>= 1) v += __shfl_xor_sync(0xffffffffu, v, o);
    __syncthreads();
    if (lane == 0) sh[w] = v;
    __syncthreads();
    float r = 0.f;
    #pragma unroll
    for (int i = 0; i < 8; i++) r += sh[i];
    return r;
}

__global__ void ln_h_kernel(const float* __restrict__ x, const float* __restrict__ g,
                            const float* __restrict__ b, unsigned short* __restrict__ oh) {
    __shared__ float sh[8];
    int row = blockIdx.x;
    const float* xr = x + (size_t)row * DIM;
    int t = threadIdx.x;
    float v0[4];
    float s = 0.f;
    #pragma unroll
    for (int u = 0; u < 4; u++) { v0[u] = xr[t + u * 256]; s += v0[u]; }
    s = block_sum_256(s, sh);
    float mean = s * (1.0f / DIM);
    float vs = 0.f;
    #pragma unroll
    for (int u = 0; u < 4; u++) { float d = v0[u] - mean; vs += d * d; }
    vs = block_sum_256(vs, sh);
    float rstd = rsqrtf(vs * (1.0f / DIM) + 1e-5f);
    #pragma unroll
    for (int u = 0; u < 4; u++) {
        int c = t + u * 256;
        oh[(size_t)row * DIM + c] = f2h((v0[u] - mean) * rstd * g[c] + b[c]);
    }
}

// ---------------- weight transpose -> fp16 ----------------
__global__ void transpose_h_kernel(const float* __restrict__ in, int R, int C,
                                   unsigned short* __restrict__ out) {
    __shared__ float t[32][33];
    int c0 = blockIdx.x * 32, r0 = blockIdx.y * 32;
    #pragma unroll
    for (int u = 0; u < 4; u++) {
        int r = r0 + threadIdx.y + u * 8;
        t[threadIdx.y + u * 8][threadIdx.x] = in[(size_t)r * C + c0 + threadIdx.x];
    }
    __syncthreads();
    #pragma unroll
    for (int u = 0; u < 4; u++) {
        int c = c0 + threadIdx.y + u * 8;
        out[(size_t)c * R + r0 + threadIdx.x] = f2h(t[threadIdx.x][threadIdx.y + u * 8]);
    }
}

__global__ void transpose_qkv_kernel(const float* __restrict__ wq, const float* __restrict__ wk,
                                     const float* __restrict__ wv, unsigned short* __restrict__ out) {
    __shared__ float t[32][33];
    const float* in = (blockIdx.z == 0) ? wq : (blockIdx.z == 1) ? wk : wv;
    unsigned short* oz = out + (size_t)blockIdx.z * DIM * DIM;
    int c0 = blockIdx.x * 32, r0 = blockIdx.y * 32;
    #pragma unroll
    for (int u = 0; u < 4; u++) {
        int r = r0 + threadIdx.y + u * 8;
        t[threadIdx.y + u * 8][threadIdx.x] = in[(size_t)r * DIM + c0 + threadIdx.x];
    }
    __syncthreads();
    #pragma unroll
    for (int u = 0; u < 4; u++) {
        int c = c0 + threadIdx.y + u * 8;
        oz[(size_t)c * DIM + r0 + threadIdx.x] = f2h(t[threadIdx.x][threadIdx.y + u * 8]);
    }
}

__global__ void concat_bias_kernel(const float* __restrict__ bq, const float* __restrict__ bk,
                                   const float* __restrict__ bv, float* __restrict__ out) {
    int i = blockIdx.x * 256 + threadIdx.x;
    if (i < DIM) out[i] = bq[i];
    else if (i < 2 * DIM) out[i] = bk[i - DIM];
    else if (i < 3 * DIM) out[i] = bv[i - 2 * DIM];
}

// ---------------- fp16 GEMM: C = A_f16 @ B_f16^T ----------------
// 128x128 CTA tile, BK=32, 2 tiles/stage (A, B), 4 stages, 2 CTAs/SM.
#define TILEB 10240u
#define STAGES 4
#define GEMM_SMEM (STAGES * 2 * 10240)

__global__ __launch_bounds__(256, 2)
void gemm_mma_kernel(const unsigned short* __restrict__ A, const unsigned short* __restrict__ B,
                     const float* __restrict__ bias, const float* __restrict__ res,
                     float* __restrict__ outF, unsigned short* __restrict__ outH,
                     int N, int K, int gelu) {
    extern __shared__ char smem[];
    const uint32_t sb = smem_u32(smem);
    const int tid  = threadIdx.x;
    const int wid  = tid >> 5;
    const int lane = tid & 31;
    const int wm = wid >> 2;
    const int wn = wid & 3;
    const int bm = blockIdx.y * 128;
    const int bn = blockIdx.x * 128;
    const int g  = lane >> 2;
    const int t4 = lane & 3;

    const uint32_t aOff = (uint32_t)((((lane >> 3) & 1) * 8 + (lane & 7)) * 80 + (lane >> 4) * 16);
    const uint32_t bOff = (uint32_t)(((lane >> 4) * 8 + (lane & 7)) * 80 + ((lane >> 3) & 1) * 16);

    float acc[4][4][4];
    #pragma unroll
    for (int i = 0; i < 4; i++)
        #pragma unroll
        for (int j = 0; j < 4; j++)
            #pragma unroll
            for (int q = 0; q < 4; q++) acc[i][j][q] = 0.f;

    const int NCH = K >> 5;
    const unsigned short* gsrc[2] = {A, B};
    const int rbase[2] = {bm, bn};

    auto load_chunk = [&](int stage, int k0) {
        #pragma unroll
        for (int t = 0; t < 2; t++) {
            uint32_t dst = sb + (uint32_t)(stage * 2 + t) * TILEB;
            const unsigned short* gp = gsrc[t];
            #pragma unroll
            for (int u = 0; u < 2; u++) {
                int idx = tid + 256 * u;
                int r = idx >> 2;
                int cc = idx & 3;
                cp_async16(dst + (uint32_t)(r * 80 + cc * 16),
                           gp + (size_t)(rbase[t] + r) * K + k0 + cc * 8);
            }
        }
        CP_COMMIT();
    };

    #pragma unroll
    for (int s = 0; s < STAGES; s++) load_chunk(s, s * 32);

    int st = 0;
    for (int i = 0; i < NCH; i++) {
        CP_WAIT(STAGES - 1);
        __syncthreads();

        const uint32_t aB = sb + (uint32_t)(st * 2) * TILEB;
        const uint32_t bB = aB + TILEB;

        #pragma unroll
        for (int ks = 0; ks < 2; ks++) {
            uint32_t bf[2][4];
            #pragma unroll
            for (int np = 0; np < 2; np++) {
                uint32_t o = (uint32_t)((wn * 32 + np * 16) * 80 + ks * 32) + bOff;
                LDSM4(bf[np], bB + o);
            }
            #pragma unroll
            for (int mt = 0; mt < 4; mt++) {
                uint32_t af[4];
                uint32_t o = (uint32_t)((wm * 64 + mt * 16) * 80 + ks * 32) + aOff;
                LDSM4(af, aB + o);
                #pragma unroll
                for (int nt = 0; nt < 4; nt++) {
                    int np = nt >> 1, sub = (nt & 1) * 2;
                    MMA_F16(acc[mt][nt], af, bf[np][sub], bf[np][sub + 1]);
                }
            }
        }
        __syncthreads();

        if (i + STAGES < NCH) load_chunk(st, (i + STAGES) * 32);
        else                  CP_COMMIT();
        st = (st + 1 == STAGES) ? 0 : st + 1;
    }

    // --- epilogue ---
    #pragma unroll
    for (int mt = 0; mt < 4; mt++) {
        int r0 = bm + wm * 64 + mt * 16 + g;
        #pragma unroll
        for (int nt = 0; nt < 4; nt++) {
            int c = bn + wn * 32 + nt * 8 + t4 * 2;
            float v[4];
            v[0] = acc[mt][nt][0] + bias[c];
            v[1] = acc[mt][nt][1] + bias[c + 1];
            v[2] = acc[mt][nt][2] + bias[c];
            v[3] = acc[mt][nt][3] + bias[c + 1];
            if (gelu) {
                #pragma unroll
                for (int q = 0; q < 4; q++)
                    v[q] = 0.5f * v[q] * (1.0f + erff(v[q] * 0.70710678118654752f));
            }
            if (res) {
                v[0] += res[(size_t)r0 * N + c];
                v[1] += res[(size_t)r0 * N + c + 1];
                v[2] += res[(size_t)(r0 + 8) * N + c];
                v[3] += res[(size_t)(r0 + 8) * N + c + 1];
            }
            if (outF) {
                *(float2*)(outF + (size_t)r0 * N + c)       = make_float2(v[0], v[1]);
                *(float2*)(outF + (size_t)(r0 + 8) * N + c) = make_float2(v[2], v[3]);
            } else {
                *(uint32_t*)(outH + (size_t)r0 * N + c)       = pack2_h(v[0], v[1]);
                *(uint32_t*)(outH + (size_t)(r0 + 8) * N + c) = pack2_h(v[2], v[3]);
            }
        }
    }
}

// ---------------- flash attention, plain fp16 ----------------
#define ATILE 9216u
#define ATT_SMEM (2 * 2 * 9216)

__global__ __launch_bounds__(128)
void attn_mma_kernel(const unsigned short* __restrict__ qkv,
                     unsigned short* __restrict__ O) {
    extern __shared__ char smem[];
    const uint32_t sb = smem_u32(smem);
    const int h  = blockIdx.y;
    const int q0 = blockIdx.x * 64;
    const int tid = threadIdx.x;
    const int w = tid >> 5, lane = tid & 31;
    const int g = lane >> 2, t4 = lane & 3;
    const int qcol = h * HDK, kcol = DIM + h * HDK, vcol = 2 * DIM + h * HDK;

    const uint32_t aOff = (uint32_t)((((lane >> 3) & 1) * 8 + (lane & 7)) * 144 + (lane >> 4) * 16);
    const uint32_t bOff = (uint32_t)(((lane >> 4) * 8 + (lane & 7)) * 144 + ((lane >> 3) & 1) * 16);
    const uint32_t vOff = (uint32_t)((lane & 15) * 144 + (lane >> 4) * 16);

    #define AK(s) (sb + (uint32_t)(s) * 2u * ATILE)
    #define AV(s) (AK(s) + ATILE)

    // stage Q through smem into registers
    #pragma unroll
    for (int u = 0; u < 4; u++) {
        int idx = tid + u * 128;
        int row = idx >> 3, c16 = idx & 7;
        cp_async16(AK(0) + (uint32_t)(row * 144 + c16 * 16),
                   qkv + (size_t)(q0 + row) * QKVN + qcol + c16 * 8);
    }
    CP_COMMIT(); CP_WAIT(0); __syncthreads();

    uint32_t qh[4][4];
    #pragma unroll
    for (int ks = 0; ks < 4; ks++) {
        uint32_t o = (uint32_t)(w * 16 * 144 + ks * 32);
        LDSM4(qh[ks], AK(0) + o + aOff);
    }
    __syncthreads();

    auto load_kv = [&](int st, int kt) {
        #pragma unroll
        for (int u = 0; u < 4; u++) {
            int idx = tid + u * 128;
            int row = idx >> 3, c16 = idx & 7;
            uint32_t off = (uint32_t)(row * 144 + c16 * 16);
            cp_async16(AK(st) + off, qkv + (size_t)(kt + row) * QKVN + kcol + c16 * 8);
            cp_async16(AV(st) + off, qkv + (size_t)(kt + row) * QKVN + vcol + c16 * 8);
        }
        CP_COMMIT();
    };
    load_kv(0, 0);
    load_kv(1, 64);

    float of[8][4];
    #pragma unroll
    for (int j = 0; j < 8; j++)
        #pragma unroll
        for (int q = 0; q < 4; q++) of[j][q] = 0.f;
    float m0 = -1e30f, m1 = -1e30f, l0 = 0.f, l1 = 0.f;

    for (int it = 0; it < SQ / 64; it++) {
        CP_WAIT(1);
        __syncthreads();
        const int st = it & 1;

        float sf[8][4];
        #pragma unroll
        for (int j = 0; j < 8; j++)
            #pragma unroll
            for (int q = 0; q < 4; q++) sf[j][q] = 0.f;

        #pragma unroll
        for (int ks = 0; ks < 4; ks++) {
            #pragma unroll
            for (int nb = 0; nb < 4; nb++) {
                uint32_t kf[4];
                LDSM4(kf, AK(st) + (uint32_t)(nb * 16 * 144 + ks * 32) + bOff);
                MMA_F16(sf[2*nb],   qh[ks], kf[0], kf[1]);
                MMA_F16(sf[2*nb+1], qh[ks], kf[2], kf[3]);
            }
        }

        float mx0 = -1e30f, mx1 = -1e30f;
        #pragma unroll
        for (int j = 0; j < 8; j++) {
            #pragma unroll
            for (int q = 0; q < 4; q++) sf[j][q] *= 0.125f;
            mx0 = fmaxf(mx0, fmaxf(sf[j][0], sf[j][1]));
            mx1 = fmaxf(mx1, fmaxf(sf[j][2], sf[j][3]));
        }
        mx0 = fmaxf(mx0, __shfl_xor_sync(0xffffffffu, mx0, 1));
        mx0 = fmaxf(mx0, __shfl_xor_sync(0xffffffffu, mx0, 2));
        mx1 = fmaxf(mx1, __shfl_xor_sync(0xffffffffu, mx1, 1));
        mx1 = fmaxf(mx1, __shfl_xor_sync(0xffffffffu, mx1, 2));
        float mn0 = fmaxf(m0, mx0), mn1 = fmaxf(m1, mx1);
        float sc0 = __expf(m0 - mn0), sc1 = __expf(m1 - mn1);
        m0 = mn0; m1 = mn1;
        float s0 = 0.f, s1 = 0.f;
        #pragma unroll
        for (int j = 0; j < 8; j++) {
            sf[j][0] = __expf(sf[j][0] - mn0); s0 += sf[j][0];
            sf[j][1] = __expf(sf[j][1] - mn0); s0 += sf[j][1];
            sf[j][2] = __expf(sf[j][2] - mn1); s1 += sf[j][2];
            sf[j][3] = __expf(sf[j][3] - mn1); s1 += sf[j][3];
        }
        s0 += __shfl_xor_sync(0xffffffffu, s0, 1);
        s0 += __shfl_xor_sync(0xffffffffu, s0, 2);
        s1 += __shfl_xor_sync(0xffffffffu, s1, 1);
        s1 += __shfl_xor_sync(0xffffffffu, s1, 2);
        l0 = l0 * sc0 + s0;
        l1 = l1 * sc1 + s1;
        #pragma unroll
        for (int j = 0; j < 8; j++) {
            of[j][0] *= sc0; of[j][1] *= sc0;
            of[j][2] *= sc1; of[j][3] *= sc1;
        }

        #pragma unroll
        for (int jp = 0; jp < 4; jp++) {
            uint32_t p0 = pack2_h(sf[2*jp][0],   sf[2*jp][1]);
            uint32_t p1 = pack2_h(sf[2*jp][2],   sf[2*jp][3]);
            uint32_t p2 = pack2_h(sf[2*jp+1][0], sf[2*jp+1][1]);
            uint32_t p3 = pack2_h(sf[2*jp+1][2], sf[2*jp+1][3]);
            #pragma unroll
            for (int nb = 0; nb < 4; nb++) {
                uint32_t vf[4];
                LDSM4T(vf, AV(st) + (uint32_t)(jp * 16 * 144 + nb * 16 * 2) + vOff);
                MMA_F16R(of[2*nb],   p0, p1, p2, p3, vf[0], vf[1]);
                MMA_F16R(of[2*nb+1], p0, p1, p2, p3, vf[2], vf[3]);
            }
        }

        __syncthreads();
        if (it + 2 < SQ / 64) load_kv(st, (it + 2) * 64);
        else                  CP_COMMIT();
    }

    float inv0 = 1.0f / l0, inv1 = 1.0f / l1;
    int r0 = q0 + w * 16 + g;
    #pragma unroll
    for (int j = 0; j < 8; j++) {
        int d = 8 * j + 2 * t4;
        *(uint32_t*)(O + (size_t)h * SQ * HDK + (size_t)r0 * HDK + d) =
            pack2_h(of[j][0] * inv0, of[j][1] * inv0);
        *(uint32_t*)(O + (size_t)h * SQ * HDK + (size_t)(r0 + 8) * HDK + d) =
            pack2_h(of[j][2] * inv1, of[j][3] * inv1);
    }
}

// ---------------- launch ----------------
extern "C" void kernel_launch(void* const* d_in, const int* in_sizes, int n_in,
                              void* d_out, int out_size) {
    const float* x     = (const float*)d_in[0];
    const float* wq    = (const float*)d_in[1];
    const float* bq    = (const float*)d_in[2];
    const float* wk    = (const float*)d_in[3];
    const float* bk    = (const float*)d_in[4];
    const float* wv    = (const float*)d_in[5];
    const float* bv    = (const float*)d_in[6];
    const float* wo    = (const float*)d_in[7];
    const float* bo    = (const float*)d_in[8];
    const float* w1    = (const float*)d_in[9];
    const float* b1    = (const float*)d_in[10];
    const float* w2    = (const float*)d_in[11];
    const float* b2    = (const float*)d_in[12];
    const float* ln1_g = (const float*)d_in[13];
    const float* ln1_b = (const float*)d_in[14];
    const float* ln2_g = (const float*)d_in[15];
    const float* ln2_b = (const float*)d_in[16];
    float* out = (float*)d_out;

    unsigned short *hh, *qkv, *ao, *f, *wqkvh, *woh, *w1h, *w2h;
    float *x1, *bqkv;
    cudaGetSymbolAddress((void**)&hh,   g_h);
    cudaGetSymbolAddress((void**)&qkv,  g_qkv);
    cudaGetSymbolAddress((void**)&ao,   g_ao);
    cudaGetSymbolAddress((void**)&x1,   g_x1);
    cudaGetSymbolAddress((void**)&f,    g_f);
    cudaGetSymbolAddress((void**)&wqkvh, g_wqkv);
    cudaGetSymbolAddress((void**)&woh,  g_wo);
    cudaGetSymbolAddress((void**)&w1h,  g_w1);
    cudaGetSymbolAddress((void**)&w2h,  g_w2);
    cudaGetSymbolAddress((void**)&bqkv, g_bqkv);

    cudaFuncSetAttribute(gemm_mma_kernel,
                         cudaFuncAttributeMaxDynamicSharedMemorySize, GEMM_SMEM);
    cudaFuncSetAttribute(attn_mma_kernel,
                         cudaFuncAttributeMaxDynamicSharedMemorySize, ATT_SMEM);

    dim3 tb(32, 8);

    // prep
    ln_h_kernel<<<SQ, 256>>>(x, ln1_g, ln1_b, hh);
    transpose_qkv_kernel<<<dim3(DIM/32, DIM/32, 3), tb>>>(wq, wk, wv, wqkvh);
    concat_bias_kernel<<<QKVN/256, 256>>>(bq, bk, bv, bqkv);
    transpose_h_kernel<<<dim3(DIM/32,  DIM/32),  tb>>>(wo, DIM,  DIM,  woh);
    transpose_h_kernel<<<dim3(MLPD/32, DIM/32),  tb>>>(w1, DIM,  MLPD, w1h);
    // QKV fused GEMM -> fp16
    gemm_mma_kernel<<<dim3(QKVN/128, SQ/128), 256, GEMM_SMEM>>>(
        hh, wqkvh, bqkv, nullptr, nullptr, qkv, QKVN, DIM, 0);
    transpose_h_kernel<<<dim3(DIM/32,  MLPD/32), tb>>>(w2, MLPD, DIM,  w2h);
    // attention -> ao fp16
    attn_mma_kernel<<<dim3(SQ/64, NH), 128, ATT_SMEM>>>(qkv, ao);
    // O-proj + residual(x) -> x1 fp32
    gemm_mma_kernel<<<dim3(DIM/128, SQ/128), 256, GEMM_SMEM>>>(
        ao, woh, bo, x, x1, nullptr, DIM, DIM, 0);
    // LN2 -> fp16
    ln_h_kernel<<<SQ, 256>>>(x1, ln2_g, ln2_b, hh);
    // FFN1 + GELU -> f fp16
    gemm_mma_kernel<<<dim3(MLPD/128, SQ/128), 256, GEMM_SMEM>>>(
        hh, w1h, b1, nullptr, nullptr, f, MLPD, DIM, 1);
    // FFN2 + residual(x1) -> out fp32
    gemm_mma_kernel<<<dim3(DIM/128, SQ/128), 256, GEMM_SMEM>>>(
        f, w2h, b2, x1, out, nullptr, DIM, MLPD, 0);
}